// round 7
// baseline (speedup 1.0000x reference)
#include <cuda_runtime.h>
#include <cuda_bf16.h>

#define MAX_N 100000
#define MAX_E 1600000
#define MAX_G 256
#define SCAN_T 512

// Padded feature strides (128B-line aligned rows)
#define LD54  64
#define LD108 128
#define LD216 224

// ---------------------------------------------------------------------------
// Static scratch
// ---------------------------------------------------------------------------
__device__ float g_bufA[MAX_N * LD216];
__device__ float g_bufB[MAX_N * LD216];
__device__ float g_dinv[MAX_N];
__device__ float g_pooled[MAX_G * 216];
__device__ float g_fc1[MAX_G * 1024];
__device__ int   g_counts[MAX_N];
__device__ int   g_indptr[MAX_N + 1];
__device__ int   g_cursor[MAX_N];
__device__ int   g_blockSums[(MAX_N + SCAN_T - 1) / SCAN_T];
__device__ int   g_done;
__device__ int   g_csrc[MAX_E];

// ---------------------------------------------------------------------------
// CSR construction
// ---------------------------------------------------------------------------
__global__ void zero_counts_kernel(int* counts, int* done, int N) {
    int i = blockIdx.x * blockDim.x + threadIdx.x;
    if (i < N) counts[i] = 0;
    if (i == 0) *done = 0;
}

__global__ void count_kernel(const int* __restrict__ col, int* counts, int E) {
    int i = blockIdx.x * blockDim.x + threadIdx.x;
    if (i < E) atomicAdd(&counts[col[i]], 1);
}

// Single-pass: per-block sums, last block scans the partials (exclusive).
__global__ void bsum_scan_kernel(const int* __restrict__ counts, int* blockSums,
                                 int* done, int N, int nb) {
    __shared__ int s[SCAN_T];
    __shared__ bool last;
    int tid = threadIdx.x;
    int i = blockIdx.x * SCAN_T + tid;
    s[tid] = (i < N) ? counts[i] : 0;
    __syncthreads();
    #pragma unroll
    for (int off = SCAN_T / 2; off > 0; off >>= 1) {
        if (tid < off) s[tid] += s[tid + off];
        __syncthreads();
    }
    if (tid == 0) {
        blockSums[blockIdx.x] = s[0];
        __threadfence();
        int p = atomicAdd(done, 1);
        last = (p == nb - 1);
    }
    __syncthreads();
    if (!last) return;
    // last block: exclusive scan of nb partials (nb <= SCAN_T)
    int v = (tid < nb) ? blockSums[tid] : 0;
    s[tid] = v;
    __syncthreads();
    #pragma unroll
    for (int off = 1; off < SCAN_T; off <<= 1) {
        int u = (tid >= off) ? s[tid - off] : 0;
        __syncthreads();
        s[tid] += u;
        __syncthreads();
    }
    if (tid < nb) blockSums[tid] = s[tid] - v;
}

// Per-block inclusive scan + global offset -> indptr/cursor; also dinv.
__global__ void scan_write_dinv_kernel(const int* __restrict__ counts, const int* __restrict__ blockSums,
                                       int* __restrict__ indptr, int* __restrict__ cursor,
                                       float* __restrict__ dinv, int N) {
    __shared__ int s[SCAN_T];
    int tid = threadIdx.x;
    int i = blockIdx.x * SCAN_T + tid;
    int v = (i < N) ? counts[i] : 0;
    s[tid] = v;
    __syncthreads();
    #pragma unroll
    for (int off = 1; off < SCAN_T; off <<= 1) {
        int u = (tid >= off) ? s[tid - off] : 0;
        __syncthreads();
        s[tid] += u;
        __syncthreads();
    }
    int excl = blockSums[blockIdx.x] + s[tid] - v;
    if (i < N) {
        indptr[i] = excl;
        cursor[i] = excl;
        dinv[i] = rsqrtf((float)v + 1.0f);
    }
    if (i == N - 1) indptr[N] = excl + v;
}

__global__ void fill_kernel(const int* __restrict__ row, const int* __restrict__ col,
                            int* cursor, int* __restrict__ csrc, int E) {
    int e = blockIdx.x * blockDim.x + threadIdx.x;
    if (e >= E) return;
    int pos = atomicAdd(&cursor[col[e]], 1);
    csrc[pos] = row[e];
}

// ---------------------------------------------------------------------------
// Gathers. out[v] = dinv[v] * (sum_src hs[src] + hs[v]) where hs is pre-scaled
// by dinv at the source (GEMM epilogue). Layer 1 variant scales x on the fly.
// One warp per node, 4 ILP chains, lanes 0..26 carry float2/float4.
// ---------------------------------------------------------------------------
__global__ void gather54_l1_kernel(const float* __restrict__ x,   // compact lda=54
                                   const int* __restrict__ indptr,
                                   const int* __restrict__ csrc,
                                   const float* __restrict__ dinv,
                                   float* __restrict__ out, int N) {  // lda=LD54
    const int F = 54, NL = 27;
    int warp = (blockIdx.x * blockDim.x + threadIdx.x) >> 5;
    int lane = threadIdx.x & 31;
    if (warp >= N) return;
    int v = warp;
    int s = indptr[v], e = indptr[v + 1];
    float2 a0 = {0.f, 0.f}, a1 = {0.f, 0.f}, a2 = {0.f, 0.f}, a3 = {0.f, 0.f};
    bool act = lane < NL;
    size_t off2 = (size_t)lane * 2;
    int i = s;
    for (; i + 3 < e; i += 4) {
        int s0 = csrc[i], s1 = csrc[i + 1], s2 = csrc[i + 2], s3 = csrc[i + 3];
        float d0 = dinv[s0], d1 = dinv[s1], d2 = dinv[s2], d3 = dinv[s3];
        if (act) {
            float2 x0 = *reinterpret_cast<const float2*>(x + (size_t)s0 * F + off2);
            float2 x1 = *reinterpret_cast<const float2*>(x + (size_t)s1 * F + off2);
            float2 x2 = *reinterpret_cast<const float2*>(x + (size_t)s2 * F + off2);
            float2 x3 = *reinterpret_cast<const float2*>(x + (size_t)s3 * F + off2);
            a0.x += d0 * x0.x; a0.y += d0 * x0.y;
            a1.x += d1 * x1.x; a1.y += d1 * x1.y;
            a2.x += d2 * x2.x; a2.y += d2 * x2.y;
            a3.x += d3 * x3.x; a3.y += d3 * x3.y;
        }
    }
    for (; i < e; i++) {
        int s0 = csrc[i];
        float d0 = dinv[s0];
        if (act) {
            float2 x0 = *reinterpret_cast<const float2*>(x + (size_t)s0 * F + off2);
            a0.x += d0 * x0.x; a0.y += d0 * x0.y;
        }
    }
    if (act) {
        float dv = dinv[v];
        float2 xv = *reinterpret_cast<const float2*>(x + (size_t)v * F + off2);
        float2 r;
        r.x = dv * ((a0.x + a1.x) + (a2.x + a3.x) + dv * xv.x);
        r.y = dv * ((a0.y + a1.y) + (a2.y + a3.y) + dv * xv.y);
        *reinterpret_cast<float2*>(out + (size_t)v * LD54 + off2) = r;
    }
}

__global__ void gather54_pre_kernel(const float* __restrict__ hs,  // lda=LD54, pre-scaled
                                    const int* __restrict__ indptr,
                                    const int* __restrict__ csrc,
                                    const float* __restrict__ dinv,
                                    float* __restrict__ out, int N) {  // lda=LD54
    const int NL = 27;
    int warp = (blockIdx.x * blockDim.x + threadIdx.x) >> 5;
    int lane = threadIdx.x & 31;
    if (warp >= N) return;
    int v = warp;
    int s = indptr[v], e = indptr[v + 1];
    float2 a0 = {0.f, 0.f}, a1 = {0.f, 0.f}, a2 = {0.f, 0.f}, a3 = {0.f, 0.f};
    bool act = lane < NL;
    size_t off2 = (size_t)lane * 2;
    int i = s;
    for (; i + 3 < e; i += 4) {
        int s0 = csrc[i], s1 = csrc[i + 1], s2 = csrc[i + 2], s3 = csrc[i + 3];
        if (act) {
            float2 x0 = *reinterpret_cast<const float2*>(hs + (size_t)s0 * LD54 + off2);
            float2 x1 = *reinterpret_cast<const float2*>(hs + (size_t)s1 * LD54 + off2);
            float2 x2 = *reinterpret_cast<const float2*>(hs + (size_t)s2 * LD54 + off2);
            float2 x3 = *reinterpret_cast<const float2*>(hs + (size_t)s3 * LD54 + off2);
            a0.x += x0.x; a0.y += x0.y;
            a1.x += x1.x; a1.y += x1.y;
            a2.x += x2.x; a2.y += x2.y;
            a3.x += x3.x; a3.y += x3.y;
        }
    }
    for (; i < e; i++) {
        int s0 = csrc[i];
        if (act) {
            float2 x0 = *reinterpret_cast<const float2*>(hs + (size_t)s0 * LD54 + off2);
            a0.x += x0.x; a0.y += x0.y;
        }
    }
    if (act) {
        float dv = dinv[v];
        float2 xv = *reinterpret_cast<const float2*>(hs + (size_t)v * LD54 + off2);
        float2 r;
        r.x = dv * ((a0.x + a1.x) + (a2.x + a3.x) + xv.x);
        r.y = dv * ((a0.y + a1.y) + (a2.y + a3.y) + xv.y);
        *reinterpret_cast<float2*>(out + (size_t)v * LD54 + off2) = r;
    }
}

__global__ void gather108_pre_kernel(const float* __restrict__ hs,  // lda=LD108, pre-scaled
                                     const int* __restrict__ indptr,
                                     const int* __restrict__ csrc,
                                     const float* __restrict__ dinv,
                                     float* __restrict__ out, int N) {  // lda=LD108
    const int NL = 27;
    int warp = (blockIdx.x * blockDim.x + threadIdx.x) >> 5;
    int lane = threadIdx.x & 31;
    if (warp >= N) return;
    int v = warp;
    int s = indptr[v], e = indptr[v + 1];
    float4 a0 = {0.f, 0.f, 0.f, 0.f}, a1 = {0.f, 0.f, 0.f, 0.f};
    float4 a2 = {0.f, 0.f, 0.f, 0.f}, a3 = {0.f, 0.f, 0.f, 0.f};
    bool act = lane < NL;
    size_t off4 = (size_t)lane * 4;
    int i = s;
    for (; i + 3 < e; i += 4) {
        int s0 = csrc[i], s1 = csrc[i + 1], s2 = csrc[i + 2], s3 = csrc[i + 3];
        if (act) {
            float4 x0 = *reinterpret_cast<const float4*>(hs + (size_t)s0 * LD108 + off4);
            float4 x1 = *reinterpret_cast<const float4*>(hs + (size_t)s1 * LD108 + off4);
            float4 x2 = *reinterpret_cast<const float4*>(hs + (size_t)s2 * LD108 + off4);
            float4 x3 = *reinterpret_cast<const float4*>(hs + (size_t)s3 * LD108 + off4);
            a0.x += x0.x; a0.y += x0.y; a0.z += x0.z; a0.w += x0.w;
            a1.x += x1.x; a1.y += x1.y; a1.z += x1.z; a1.w += x1.w;
            a2.x += x2.x; a2.y += x2.y; a2.z += x2.z; a2.w += x2.w;
            a3.x += x3.x; a3.y += x3.y; a3.z += x3.z; a3.w += x3.w;
        }
    }
    for (; i < e; i++) {
        int s0 = csrc[i];
        if (act) {
            float4 x0 = *reinterpret_cast<const float4*>(hs + (size_t)s0 * LD108 + off4);
            a0.x += x0.x; a0.y += x0.y; a0.z += x0.z; a0.w += x0.w;
        }
    }
    if (act) {
        float dv = dinv[v];
        float4 xv = *reinterpret_cast<const float4*>(hs + (size_t)v * LD108 + off4);
        float4 r;
        r.x = dv * ((a0.x + a1.x) + (a2.x + a3.x) + xv.x);
        r.y = dv * ((a0.y + a1.y) + (a2.y + a3.y) + xv.y);
        r.z = dv * ((a0.z + a1.z) + (a2.z + a3.z) + xv.z);
        r.w = dv * ((a0.w + a1.w) + (a2.w + a3.w) + xv.w);
        *reinterpret_cast<float4*>(out + (size_t)v * LD108 + off4) = r;
    }
}

// ---------------------------------------------------------------------------
// SGEMM 64x64x16, 4x4 microtile, 256 threads, strided A/C, optional dinv scale.
// C[M,Nc](ldc) = A[M,K](lda) @ B[K,Nc](ldb) (+bias)(relu)(*dinv[row])
// ---------------------------------------------------------------------------
template <bool RELU_OUT, bool BIAS, bool SCALE>
__global__ void gemm_kernel(const float* __restrict__ A, int lda,
                            const float* __restrict__ B, int ldb,
                            const float* __restrict__ bias,
                            const float* __restrict__ dinvv,
                            float* __restrict__ C, int ldc,
                            int M, int K, int Nc) {
    const int BM = 64, BN = 64, BK = 16;
    __shared__ __align__(16) float As[BK][BM + 4];
    __shared__ __align__(16) float Bs[BK][BN];

    int block_row = blockIdx.y * BM;
    int block_col = blockIdx.x * BN;
    int tid = threadIdx.x;
    int tr = tid / 16;
    int tc = tid % 16;

    float acc[4][4] = {};

    for (int k0 = 0; k0 < K; k0 += BK) {
        #pragma unroll
        for (int i = tid; i < BM * BK; i += 256) {
            int r = i / BK, c = i % BK;
            int gr = block_row + r, gk = k0 + c;
            As[c][r] = (gr < M && gk < K) ? A[(size_t)gr * lda + gk] : 0.f;
        }
        #pragma unroll
        for (int i = tid; i < BK * BN; i += 256) {
            int r = i / BN, c = i % BN;
            int gk = k0 + r, gc = block_col + c;
            Bs[r][c] = (gk < K && gc < Nc) ? B[(size_t)gk * ldb + gc] : 0.f;
        }
        __syncthreads();

        #pragma unroll
        for (int k = 0; k < BK; k++) {
            float4 a = *reinterpret_cast<const float4*>(&As[k][tr * 4]);
            float4 b = *reinterpret_cast<const float4*>(&Bs[k][tc * 4]);
            float av[4] = {a.x, a.y, a.z, a.w};
            float bv[4] = {b.x, b.y, b.z, b.w};
            #pragma unroll
            for (int i = 0; i < 4; i++)
                #pragma unroll
                for (int j = 0; j < 4; j++)
                    acc[i][j] += av[i] * bv[j];
        }
        __syncthreads();
    }

    #pragma unroll
    for (int i = 0; i < 4; i++) {
        int gr = block_row + tr * 4 + i;
        if (gr >= M) continue;
        float sc = SCALE ? dinvv[gr] : 1.0f;
        #pragma unroll
        for (int j = 0; j < 4; j++) {
            int gc = block_col + tc * 4 + j;
            if (gc >= Nc) continue;
            float v = acc[i][j];
            if (BIAS) v += bias[gc];
            if (RELU_OUT) v = fmaxf(v, 0.f);
            if (SCALE) v *= sc;
            C[(size_t)gr * ldc + gc] = v;
        }
    }
}

// ---------------------------------------------------------------------------
// Per-graph mean pool. One block per graph, sorted batch. h stride LD216.
// ---------------------------------------------------------------------------
__global__ void pool_kernel(const float* __restrict__ h, const int* __restrict__ batch,
                            float* __restrict__ pooled, int N, int F) {
    int g = blockIdx.x;
    int lo = 0, hi = N;
    while (lo < hi) { int m = (lo + hi) >> 1; if (batch[m] < g) lo = m + 1; else hi = m; }
    int start = lo;
    lo = start; hi = N;
    while (lo < hi) { int m = (lo + hi) >> 1; if (batch[m] < g + 1) lo = m + 1; else hi = m; }
    int end = lo;

    int f = threadIdx.x;
    if (f >= F) return;
    float acc = 0.f;
    for (int v = start; v < end; v++)
        acc += h[(size_t)v * LD216 + f];
    float cnt = (float)(end - start);
    pooled[g * F + f] = acc / fmaxf(cnt, 1.0f);
}

// ---------------------------------------------------------------------------
// Launch
// ---------------------------------------------------------------------------
static inline dim3 ggrid(int M, int Nc) {
    return dim3((Nc + 63) / 64, (M + 63) / 64);
}

extern "C" void kernel_launch(void* const* d_in, const int* in_sizes, int n_in,
                              void* d_out, int out_size) {
    const float* x    = (const float*)d_in[0];
    const int*   ei   = (const int*)d_in[1];
    const int*   batch= (const int*)d_in[2];
    const float* W1   = (const float*)d_in[3];
    const float* b1   = (const float*)d_in[4];
    const float* W2   = (const float*)d_in[5];
    const float* b2   = (const float*)d_in[6];
    const float* W3   = (const float*)d_in[7];
    const float* b3   = (const float*)d_in[8];
    const float* Wf1  = (const float*)d_in[9];
    const float* bf1  = (const float*)d_in[10];
    const float* Wf2  = (const float*)d_in[11];
    const float* bf2  = (const float*)d_in[12];

    int N = in_sizes[0] / 54;
    int E = in_sizes[1] / 2;
    int G = out_size / 128;
    const int* row = ei;
    const int* col = ei + E;

    float *bufA, *bufB, *dinv, *pooled, *fc1;
    int *counts, *indptr, *cursor, *csrc, *blockSums, *done;
    cudaGetSymbolAddress((void**)&bufA, g_bufA);
    cudaGetSymbolAddress((void**)&bufB, g_bufB);
    cudaGetSymbolAddress((void**)&dinv, g_dinv);
    cudaGetSymbolAddress((void**)&pooled, g_pooled);
    cudaGetSymbolAddress((void**)&fc1, g_fc1);
    cudaGetSymbolAddress((void**)&counts, g_counts);
    cudaGetSymbolAddress((void**)&indptr, g_indptr);
    cudaGetSymbolAddress((void**)&cursor, g_cursor);
    cudaGetSymbolAddress((void**)&csrc, g_csrc);
    cudaGetSymbolAddress((void**)&blockSums, g_blockSums);
    cudaGetSymbolAddress((void**)&done, g_done);

    const int T = 256;
    int nb = (N + SCAN_T - 1) / SCAN_T;
    int gatherGrid = (N + 7) / 8;

    // --- CSR build (launches 0..4) ---
    zero_counts_kernel<<<(N + T - 1) / T, T>>>(counts, done, N);
    count_kernel<<<(E + T - 1) / T, T>>>(col, counts, E);
    bsum_scan_kernel<<<nb, SCAN_T>>>(counts, blockSums, done, N, nb);
    scan_write_dinv_kernel<<<nb, SCAN_T>>>(counts, blockSums, indptr, cursor, dinv, N);
    fill_kernel<<<(E + T - 1) / T, T>>>(row, col, cursor, csrc, E);

    // --- Layer 1: agg(x·dinv)·dinv @ W1, relu, scale by dinv (launch 5 = gather) ---
    gather54_l1_kernel<<<gatherGrid, T>>>(x, indptr, csrc, dinv, bufA, N);
    gemm_kernel<true, true, true><<<ggrid(N, 54), 256>>>(bufA, LD54, W1, 54, b1, dinv, bufB, LD54, N, 54, 54);

    // --- Layer 2 ---
    gather54_pre_kernel<<<gatherGrid, T>>>(bufB, indptr, csrc, dinv, bufA, N);
    gemm_kernel<true, true, true><<<ggrid(N, 108), 256>>>(bufA, LD54, W2, 108, b2, dinv, bufB, LD108, N, 54, 108);

    // --- Layer 3 (no output scale; feeds pooling) ---
    gather108_pre_kernel<<<gatherGrid, T>>>(bufB, indptr, csrc, dinv, bufA, N);
    gemm_kernel<true, true, false><<<ggrid(N, 216), 256>>>(bufA, LD108, W3, 216, b3, nullptr, bufB, LD216, N, 108, 216);

    // --- Global mean pool ---
    pool_kernel<<<G, 256>>>(bufB, batch, pooled, N, 216);

    // --- MLP head ---
    gemm_kernel<true, true, false><<<ggrid(G, 1024), 256>>>(pooled, 216, Wf1, 1024, bf1, nullptr, fc1, 1024, G, 216, 1024);
    gemm_kernel<false, true, false><<<ggrid(G, 128), 256>>>(fc1, 1024, Wf2, 128, bf2, nullptr, (float*)d_out, 128, G, 1024, 128);
}

// round 9
// speedup vs baseline: 1.0021x; 1.0021x over previous
#include <cuda_runtime.h>
#include <cuda_bf16.h>
#include <cstdint>

#define MAX_N 100000
#define MAX_E 1600000
#define MAX_G 256
#define SCAN_T 512

// Padded feature strides (128B-line aligned rows)
#define LD54  64
#define LD108 128
#define LD216 224

// Packed fp32x2 FMA (B300 FFMA2): d = a*b + c elementwise on packed pairs.
#define FMA_F32X2(d, a, b, c) \
    asm("fma.rn.f32x2 %0, %1, %2, %3;" : "=l"(d) : "l"(a), "l"(b), "l"(c))

// ---------------------------------------------------------------------------
// Static scratch
// ---------------------------------------------------------------------------
__device__ float g_bufA[MAX_N * LD216];
__device__ float g_bufB[MAX_N * LD216];
__device__ float g_dinv[MAX_N];
__device__ float g_pooled[MAX_G * 216];
__device__ float g_fc1[MAX_G * 1024];
__device__ int   g_counts[MAX_N];
__device__ int   g_indptr[MAX_N + 1];
__device__ int   g_cursor[MAX_N];
__device__ int   g_blockSums[(MAX_N + SCAN_T - 1) / SCAN_T];
__device__ int   g_done;
__device__ int   g_csrc[MAX_E];

// ---------------------------------------------------------------------------
// CSR construction
// ---------------------------------------------------------------------------
__global__ void zero_counts_kernel(int* counts, int* done, int N) {
    int i = blockIdx.x * blockDim.x + threadIdx.x;
    if (i < N) counts[i] = 0;
    if (i == 0) *done = 0;
}

__global__ void count_kernel(const int* __restrict__ col, int* counts, int E) {
    int i = blockIdx.x * blockDim.x + threadIdx.x;
    if (i < E) atomicAdd(&counts[col[i]], 1);
}

// Single-pass: per-block sums, last block scans the partials (exclusive).
__global__ void bsum_scan_kernel(const int* __restrict__ counts, int* blockSums,
                                 int* done, int N, int nb) {
    __shared__ int s[SCAN_T];
    __shared__ bool last;
    int tid = threadIdx.x;
    int i = blockIdx.x * SCAN_T + tid;
    s[tid] = (i < N) ? counts[i] : 0;
    __syncthreads();
    #pragma unroll
    for (int off = SCAN_T / 2; off > 0; off >>= 1) {
        if (tid < off) s[tid] += s[tid + off];
        __syncthreads();
    }
    if (tid == 0) {
        blockSums[blockIdx.x] = s[0];
        __threadfence();
        int p = atomicAdd(done, 1);
        last = (p == nb - 1);
    }
    __syncthreads();
    if (!last) return;
    int v = (tid < nb) ? blockSums[tid] : 0;
    s[tid] = v;
    __syncthreads();
    #pragma unroll
    for (int off = 1; off < SCAN_T; off <<= 1) {
        int u = (tid >= off) ? s[tid - off] : 0;
        __syncthreads();
        s[tid] += u;
        __syncthreads();
    }
    if (tid < nb) blockSums[tid] = s[tid] - v;
}

__global__ void scan_write_dinv_kernel(const int* __restrict__ counts, const int* __restrict__ blockSums,
                                       int* __restrict__ indptr, int* __restrict__ cursor,
                                       float* __restrict__ dinv, int N) {
    __shared__ int s[SCAN_T];
    int tid = threadIdx.x;
    int i = blockIdx.x * SCAN_T + tid;
    int v = (i < N) ? counts[i] : 0;
    s[tid] = v;
    __syncthreads();
    #pragma unroll
    for (int off = 1; off < SCAN_T; off <<= 1) {
        int u = (tid >= off) ? s[tid - off] : 0;
        __syncthreads();
        s[tid] += u;
        __syncthreads();
    }
    int excl = blockSums[blockIdx.x] + s[tid] - v;
    if (i < N) {
        indptr[i] = excl;
        cursor[i] = excl;
        dinv[i] = rsqrtf((float)v + 1.0f);
    }
    if (i == N - 1) indptr[N] = excl + v;
}

__global__ void fill_kernel(const int* __restrict__ row, const int* __restrict__ col,
                            int* cursor, int* __restrict__ csrc, int E) {
    int e = blockIdx.x * blockDim.x + threadIdx.x;
    if (e >= E) return;
    int pos = atomicAdd(&cursor[col[e]], 1);
    csrc[pos] = row[e];
}

// ---------------------------------------------------------------------------
// Gathers. out[v] = dinv[v] * (sum_src hs[src] + hs[v]); hs pre-scaled by dinv
// in the GEMM epilogue. Layer-1 variant scales raw x on the fly.
// One warp per node, 4 ILP chains, lanes 0..26 carry float2/float4.
// ---------------------------------------------------------------------------
__global__ void gather54_l1_kernel(const float* __restrict__ x,   // compact lda=54
                                   const int* __restrict__ indptr,
                                   const int* __restrict__ csrc,
                                   const float* __restrict__ dinv,
                                   float* __restrict__ out, int N) {  // lda=LD54
    const int F = 54, NL = 27;
    int warp = (blockIdx.x * blockDim.x + threadIdx.x) >> 5;
    int lane = threadIdx.x & 31;
    if (warp >= N) return;
    int v = warp;
    int s = indptr[v], e = indptr[v + 1];
    float2 a0 = {0.f, 0.f}, a1 = {0.f, 0.f}, a2 = {0.f, 0.f}, a3 = {0.f, 0.f};
    bool act = lane < NL;
    size_t off2 = (size_t)lane * 2;
    int i = s;
    for (; i + 3 < e; i += 4) {
        int s0 = csrc[i], s1 = csrc[i + 1], s2 = csrc[i + 2], s3 = csrc[i + 3];
        float d0 = dinv[s0], d1 = dinv[s1], d2 = dinv[s2], d3 = dinv[s3];
        if (act) {
            float2 x0 = *reinterpret_cast<const float2*>(x + (size_t)s0 * F + off2);
            float2 x1 = *reinterpret_cast<const float2*>(x + (size_t)s1 * F + off2);
            float2 x2 = *reinterpret_cast<const float2*>(x + (size_t)s2 * F + off2);
            float2 x3 = *reinterpret_cast<const float2*>(x + (size_t)s3 * F + off2);
            a0.x += d0 * x0.x; a0.y += d0 * x0.y;
            a1.x += d1 * x1.x; a1.y += d1 * x1.y;
            a2.x += d2 * x2.x; a2.y += d2 * x2.y;
            a3.x += d3 * x3.x; a3.y += d3 * x3.y;
        }
    }
    for (; i < e; i++) {
        int s0 = csrc[i];
        float d0 = dinv[s0];
        if (act) {
            float2 x0 = *reinterpret_cast<const float2*>(x + (size_t)s0 * F + off2);
            a0.x += d0 * x0.x; a0.y += d0 * x0.y;
        }
    }
    if (act) {
        float dv = dinv[v];
        float2 xv = *reinterpret_cast<const float2*>(x + (size_t)v * F + off2);
        float2 r;
        r.x = dv * ((a0.x + a1.x) + (a2.x + a3.x) + dv * xv.x);
        r.y = dv * ((a0.y + a1.y) + (a2.y + a3.y) + dv * xv.y);
        *reinterpret_cast<float2*>(out + (size_t)v * LD54 + off2) = r;
    }
}

__global__ void gather54_pre_kernel(const float* __restrict__ hs,  // lda=LD54, pre-scaled
                                    const int* __restrict__ indptr,
                                    const int* __restrict__ csrc,
                                    const float* __restrict__ dinv,
                                    float* __restrict__ out, int N) {  // lda=LD54
    const int NL = 27;
    int warp = (blockIdx.x * blockDim.x + threadIdx.x) >> 5;
    int lane = threadIdx.x & 31;
    if (warp >= N) return;
    int v = warp;
    int s = indptr[v], e = indptr[v + 1];
    float2 a0 = {0.f, 0.f}, a1 = {0.f, 0.f}, a2 = {0.f, 0.f}, a3 = {0.f, 0.f};
    bool act = lane < NL;
    size_t off2 = (size_t)lane * 2;
    int i = s;
    for (; i + 3 < e; i += 4) {
        int s0 = csrc[i], s1 = csrc[i + 1], s2 = csrc[i + 2], s3 = csrc[i + 3];
        if (act) {
            float2 x0 = *reinterpret_cast<const float2*>(hs + (size_t)s0 * LD54 + off2);
            float2 x1 = *reinterpret_cast<const float2*>(hs + (size_t)s1 * LD54 + off2);
            float2 x2 = *reinterpret_cast<const float2*>(hs + (size_t)s2 * LD54 + off2);
            float2 x3 = *reinterpret_cast<const float2*>(hs + (size_t)s3 * LD54 + off2);
            a0.x += x0.x; a0.y += x0.y;
            a1.x += x1.x; a1.y += x1.y;
            a2.x += x2.x; a2.y += x2.y;
            a3.x += x3.x; a3.y += x3.y;
        }
    }
    for (; i < e; i++) {
        int s0 = csrc[i];
        if (act) {
            float2 x0 = *reinterpret_cast<const float2*>(hs + (size_t)s0 * LD54 + off2);
            a0.x += x0.x; a0.y += x0.y;
        }
    }
    if (act) {
        float dv = dinv[v];
        float2 xv = *reinterpret_cast<const float2*>(hs + (size_t)v * LD54 + off2);
        float2 r;
        r.x = dv * ((a0.x + a1.x) + (a2.x + a3.x) + xv.x);
        r.y = dv * ((a0.y + a1.y) + (a2.y + a3.y) + xv.y);
        *reinterpret_cast<float2*>(out + (size_t)v * LD54 + off2) = r;
    }
}

__global__ void gather108_pre_kernel(const float* __restrict__ hs,  // lda=LD108, pre-scaled
                                     const int* __restrict__ indptr,
                                     const int* __restrict__ csrc,
                                     const float* __restrict__ dinv,
                                     float* __restrict__ out, int N) {  // lda=LD108
    const int NL = 27;
    int warp = (blockIdx.x * blockDim.x + threadIdx.x) >> 5;
    int lane = threadIdx.x & 31;
    if (warp >= N) return;
    int v = warp;
    int s = indptr[v], e = indptr[v + 1];
    float4 a0 = {0.f, 0.f, 0.f, 0.f}, a1 = {0.f, 0.f, 0.f, 0.f};
    float4 a2 = {0.f, 0.f, 0.f, 0.f}, a3 = {0.f, 0.f, 0.f, 0.f};
    bool act = lane < NL;
    size_t off4 = (size_t)lane * 4;
    int i = s;
    for (; i + 3 < e; i += 4) {
        int s0 = csrc[i], s1 = csrc[i + 1], s2 = csrc[i + 2], s3 = csrc[i + 3];
        if (act) {
            float4 x0 = *reinterpret_cast<const float4*>(hs + (size_t)s0 * LD108 + off4);
            float4 x1 = *reinterpret_cast<const float4*>(hs + (size_t)s1 * LD108 + off4);
            float4 x2 = *reinterpret_cast<const float4*>(hs + (size_t)s2 * LD108 + off4);
            float4 x3 = *reinterpret_cast<const float4*>(hs + (size_t)s3 * LD108 + off4);
            a0.x += x0.x; a0.y += x0.y; a0.z += x0.z; a0.w += x0.w;
            a1.x += x1.x; a1.y += x1.y; a1.z += x1.z; a1.w += x1.w;
            a2.x += x2.x; a2.y += x2.y; a2.z += x2.z; a2.w += x2.w;
            a3.x += x3.x; a3.y += x3.y; a3.z += x3.z; a3.w += x3.w;
        }
    }
    for (; i < e; i++) {
        int s0 = csrc[i];
        if (act) {
            float4 x0 = *reinterpret_cast<const float4*>(hs + (size_t)s0 * LD108 + off4);
            a0.x += x0.x; a0.y += x0.y; a0.z += x0.z; a0.w += x0.w;
        }
    }
    if (act) {
        float dv = dinv[v];
        float4 xv = *reinterpret_cast<const float4*>(hs + (size_t)v * LD108 + off4);
        float4 r;
        r.x = dv * ((a0.x + a1.x) + (a2.x + a3.x) + xv.x);
        r.y = dv * ((a0.y + a1.y) + (a2.y + a3.y) + xv.y);
        r.z = dv * ((a0.z + a1.z) + (a2.z + a3.z) + xv.z);
        r.w = dv * ((a0.w + a1.w) + (a2.w + a3.w) + xv.w);
        *reinterpret_cast<float4*>(out + (size_t)v * LD108 + off4) = r;
    }
}

// ---------------------------------------------------------------------------
// SGEMM 64x64x16, 4x4 microtile with packed f32x2 FMA (FFMA2), 256 threads.
// C[M,Nc](ldc) = A[M,K](lda) @ B[K,Nc](ldb) (+bias)(relu)(*dinv[row])
// ---------------------------------------------------------------------------
template <bool RELU_OUT, bool BIAS, bool SCALE>
__global__ void gemm_kernel(const float* __restrict__ A, int lda,
                            const float* __restrict__ B, int ldb,
                            const float* __restrict__ bias,
                            const float* __restrict__ dinvv,
                            float* __restrict__ C, int ldc,
                            int M, int K, int Nc) {
    const int BM = 64, BN = 64, BK = 16;
    __shared__ __align__(16) float As[BK][BM + 4];
    __shared__ __align__(16) float Bs[BK][BN];

    int block_row = blockIdx.y * BM;
    int block_col = blockIdx.x * BN;
    int tid = threadIdx.x;
    int tr = tid / 16;
    int tc = tid % 16;

    // Packed accumulators: 4 rows x 2 col-pairs (each pair = 2 fp32)
    unsigned long long accp[4][2] = {};

    for (int k0 = 0; k0 < K; k0 += BK) {
        #pragma unroll
        for (int i = tid; i < BM * BK; i += 256) {
            int r = i / BK, c = i % BK;
            int gr = block_row + r, gk = k0 + c;
            As[c][r] = (gr < M && gk < K) ? A[(size_t)gr * lda + gk] : 0.f;
        }
        #pragma unroll
        for (int i = tid; i < BK * BN; i += 256) {
            int r = i / BN, c = i % BN;
            int gk = k0 + r, gc = block_col + c;
            Bs[r][c] = (gk < K && gc < Nc) ? B[(size_t)gk * ldb + gc] : 0.f;
        }
        __syncthreads();

        #pragma unroll
        for (int k = 0; k < BK; k++) {
            float4 a = *reinterpret_cast<const float4*>(&As[k][tr * 4]);
            ulonglong2 bp = *reinterpret_cast<const ulonglong2*>(&Bs[k][tc * 4]);
            float av[4] = {a.x, a.y, a.z, a.w};
            #pragma unroll
            for (int i = 0; i < 4; i++) {
                unsigned long long ap;
                uint32_t ai = __float_as_uint(av[i]);
                asm("mov.b64 %0, {%1, %1};" : "=l"(ap) : "r"(ai));
                FMA_F32X2(accp[i][0], ap, bp.x, accp[i][0]);
                FMA_F32X2(accp[i][1], ap, bp.y, accp[i][1]);
            }
        }
        __syncthreads();
    }

    #pragma unroll
    for (int i = 0; i < 4; i++) {
        int gr = block_row + tr * 4 + i;
        if (gr >= M) continue;
        float sc = SCALE ? dinvv[gr] : 1.0f;
        float vals[4];
        #pragma unroll
        for (int jp = 0; jp < 2; jp++) {
            uint32_t lo, hi;
            asm("mov.b64 {%0, %1}, %2;" : "=r"(lo), "=r"(hi) : "l"(accp[i][jp]));
            vals[jp * 2]     = __uint_as_float(lo);
            vals[jp * 2 + 1] = __uint_as_float(hi);
        }
        #pragma unroll
        for (int j = 0; j < 4; j++) {
            int gc = block_col + tc * 4 + j;
            if (gc >= Nc) continue;
            float v = vals[j];
            if (BIAS) v += bias[gc];
            if (RELU_OUT) v = fmaxf(v, 0.f);
            if (SCALE) v *= sc;
            C[(size_t)gr * ldc + gc] = v;
        }
    }
}

// ---------------------------------------------------------------------------
// Per-graph mean pool. One block per graph, sorted batch. h stride LD216.
// ---------------------------------------------------------------------------
__global__ void pool_kernel(const float* __restrict__ h, const int* __restrict__ batch,
                            float* __restrict__ pooled, int N, int F) {
    int g = blockIdx.x;
    int lo = 0, hi = N;
    while (lo < hi) { int m = (lo + hi) >> 1; if (batch[m] < g) lo = m + 1; else hi = m; }
    int start = lo;
    lo = start; hi = N;
    while (lo < hi) { int m = (lo + hi) >> 1; if (batch[m] < g + 1) lo = m + 1; else hi = m; }
    int end = lo;

    int f = threadIdx.x;
    if (f >= F) return;
    float acc = 0.f;
    for (int v = start; v < end; v++)
        acc += h[(size_t)v * LD216 + f];
    float cnt = (float)(end - start);
    pooled[g * F + f] = acc / fmaxf(cnt, 1.0f);
}

// ---------------------------------------------------------------------------
// Launch
// ---------------------------------------------------------------------------
static inline dim3 ggrid(int M, int Nc) {
    return dim3((Nc + 63) / 64, (M + 63) / 64);
}

extern "C" void kernel_launch(void* const* d_in, const int* in_sizes, int n_in,
                              void* d_out, int out_size) {
    const float* x    = (const float*)d_in[0];
    const int*   ei   = (const int*)d_in[1];
    const int*   batch= (const int*)d_in[2];
    const float* W1   = (const float*)d_in[3];
    const float* b1   = (const float*)d_in[4];
    const float* W2   = (const float*)d_in[5];
    const float* b2   = (const float*)d_in[6];
    const float* W3   = (const float*)d_in[7];
    const float* b3   = (const float*)d_in[8];
    const float* Wf1  = (const float*)d_in[9];
    const float* bf1  = (const float*)d_in[10];
    const float* Wf2  = (const float*)d_in[11];
    const float* bf2  = (const float*)d_in[12];

    int N = in_sizes[0] / 54;
    int E = in_sizes[1] / 2;
    int G = out_size / 128;
    const int* row = ei;
    const int* col = ei + E;

    float *bufA, *bufB, *dinv, *pooled, *fc1;
    int *counts, *indptr, *cursor, *csrc, *blockSums, *done;
    cudaGetSymbolAddress((void**)&bufA, g_bufA);
    cudaGetSymbolAddress((void**)&bufB, g_bufB);
    cudaGetSymbolAddress((void**)&dinv, g_dinv);
    cudaGetSymbolAddress((void**)&pooled, g_pooled);
    cudaGetSymbolAddress((void**)&fc1, g_fc1);
    cudaGetSymbolAddress((void**)&counts, g_counts);
    cudaGetSymbolAddress((void**)&indptr, g_indptr);
    cudaGetSymbolAddress((void**)&cursor, g_cursor);
    cudaGetSymbolAddress((void**)&csrc, g_csrc);
    cudaGetSymbolAddress((void**)&blockSums, g_blockSums);
    cudaGetSymbolAddress((void**)&done, g_done);

    const int T = 256;
    int nb = (N + SCAN_T - 1) / SCAN_T;
    int gatherGrid = (N + 7) / 8;

    // --- CSR build ---
    zero_counts_kernel<<<(N + T - 1) / T, T>>>(counts, done, N);
    count_kernel<<<(E + T - 1) / T, T>>>(col, counts, E);
    bsum_scan_kernel<<<nb, SCAN_T>>>(counts, blockSums, done, N, nb);
    scan_write_dinv_kernel<<<nb, SCAN_T>>>(counts, blockSums, indptr, cursor, dinv, N);
    fill_kernel<<<(E + T - 1) / T, T>>>(row, col, cursor, csrc, E);

    // --- Layer 1 ---
    gather54_l1_kernel<<<gatherGrid, T>>>(x, indptr, csrc, dinv, bufA, N);
    gemm_kernel<true, true, true><<<ggrid(N, 54), 256>>>(bufA, LD54, W1, 54, b1, dinv, bufB, LD54, N, 54, 54);

    // --- Layer 2 ---
    gather54_pre_kernel<<<gatherGrid, T>>>(bufB, indptr, csrc, dinv, bufA, N);
    gemm_kernel<true, true, true><<<ggrid(N, 108), 256>>>(bufA, LD54, W2, 108, b2, dinv, bufB, LD108, N, 54, 108);

    // --- Layer 3 (no output scale; feeds pooling) ---
    gather108_pre_kernel<<<gatherGrid, T>>>(bufB, indptr, csrc, dinv, bufA, N);
    gemm_kernel<true, true, false><<<ggrid(N, 216), 256>>>(bufA, LD108, W3, 216, b3, nullptr, bufB, LD216, N, 108, 216);

    // --- Global mean pool ---
    pool_kernel<<<G, 256>>>(bufB, batch, pooled, N, 216);

    // --- MLP head ---
    gemm_kernel<true, true, false><<<ggrid(G, 1024), 256>>>(pooled, 216, Wf1, 1024, bf1, nullptr, fc1, 1024, G, 216, 1024);
    gemm_kernel<false, true, false><<<ggrid(G, 128), 256>>>(fc1, 1024, Wf2, 128, bf2, nullptr, (float*)d_out, 128, G, 1024, 128);
}

// round 10
// speedup vs baseline: 1.0136x; 1.0114x over previous
#include <cuda_runtime.h>
#include <cuda_bf16.h>
#include <cstdint>

#define MAX_N 100000
#define MAX_E 1600000
#define MAX_G 256
#define SCAN_T 512

// Padded feature strides (128B-line aligned rows)
#define LD54  64
#define LD108 128
#define LD216 224

// Packed fp32x2 FMA (B300 FFMA2): d = a*b + c elementwise on packed pairs.
#define FMA_F32X2(d, a, b, c) \
    asm("fma.rn.f32x2 %0, %1, %2, %3;" : "=l"(d) : "l"(a), "l"(b), "l"(c))

// ---------------------------------------------------------------------------
// Static scratch
// ---------------------------------------------------------------------------
__device__ float g_bufA[MAX_N * LD216];
__device__ float g_bufB[MAX_N * LD216];
__device__ float g_dinv[MAX_N];
__device__ float g_pooled[MAX_G * 216];
__device__ float g_fc1[MAX_G * 1024];
__device__ int   g_counts[MAX_N];
__device__ int   g_indptr[MAX_N + 1];
__device__ int   g_cursor[MAX_N];
__device__ int   g_blockSums[(MAX_N + SCAN_T - 1) / SCAN_T];
__device__ int   g_done;
__device__ int   g_csrc[MAX_E];

// ---------------------------------------------------------------------------
// CSR construction
// ---------------------------------------------------------------------------
__global__ void zero_counts_kernel(int* counts, int* done, int N) {
    int i = blockIdx.x * blockDim.x + threadIdx.x;
    if (i < N) counts[i] = 0;
    if (i == 0) *done = 0;
}

__global__ void count_kernel(const int* __restrict__ col, int* counts, int E) {
    int i = blockIdx.x * blockDim.x + threadIdx.x;
    if (i < E) atomicAdd(&counts[col[i]], 1);
}

// Single-pass: per-block sums, last block scans the partials (exclusive).
__global__ void bsum_scan_kernel(const int* __restrict__ counts, int* blockSums,
                                 int* done, int N, int nb) {
    __shared__ int s[SCAN_T];
    __shared__ bool last;
    int tid = threadIdx.x;
    int i = blockIdx.x * SCAN_T + tid;
    s[tid] = (i < N) ? counts[i] : 0;
    __syncthreads();
    #pragma unroll
    for (int off = SCAN_T / 2; off > 0; off >>= 1) {
        if (tid < off) s[tid] += s[tid + off];
        __syncthreads();
    }
    if (tid == 0) {
        blockSums[blockIdx.x] = s[0];
        __threadfence();
        int p = atomicAdd(done, 1);
        last = (p == nb - 1);
    }
    __syncthreads();
    if (!last) return;
    int v = (tid < nb) ? blockSums[tid] : 0;
    s[tid] = v;
    __syncthreads();
    #pragma unroll
    for (int off = 1; off < SCAN_T; off <<= 1) {
        int u = (tid >= off) ? s[tid - off] : 0;
        __syncthreads();
        s[tid] += u;
        __syncthreads();
    }
    if (tid < nb) blockSums[tid] = s[tid] - v;
}

__global__ void scan_write_dinv_kernel(const int* __restrict__ counts, const int* __restrict__ blockSums,
                                       int* __restrict__ indptr, int* __restrict__ cursor,
                                       float* __restrict__ dinv, int N) {
    __shared__ int s[SCAN_T];
    int tid = threadIdx.x;
    int i = blockIdx.x * SCAN_T + tid;
    int v = (i < N) ? counts[i] : 0;
    s[tid] = v;
    __syncthreads();
    #pragma unroll
    for (int off = 1; off < SCAN_T; off <<= 1) {
        int u = (tid >= off) ? s[tid - off] : 0;
        __syncthreads();
        s[tid] += u;
        __syncthreads();
    }
    int excl = blockSums[blockIdx.x] + s[tid] - v;
    if (i < N) {
        indptr[i] = excl;
        cursor[i] = excl;
        dinv[i] = rsqrtf((float)v + 1.0f);
    }
    if (i == N - 1) indptr[N] = excl + v;
}

__global__ void fill_kernel(const int* __restrict__ row, const int* __restrict__ col,
                            int* cursor, int* __restrict__ csrc, int E) {
    int e = blockIdx.x * blockDim.x + threadIdx.x;
    if (e >= E) return;
    int pos = atomicAdd(&cursor[col[e]], 1);
    csrc[pos] = row[e];
}

// ---------------------------------------------------------------------------
// Gathers. out[v] = dinv[v] * (sum_src hs[src] + hs[v]); hs pre-scaled by dinv
// in the GEMM epilogue. Layer-1 variant scales raw x on the fly.
// One warp per node, 4 ILP chains, lanes 0..26 carry float2/float4.
// ---------------------------------------------------------------------------
__global__ void gather54_l1_kernel(const float* __restrict__ x,   // compact lda=54
                                   const int* __restrict__ indptr,
                                   const int* __restrict__ csrc,
                                   const float* __restrict__ dinv,
                                   float* __restrict__ out, int N) {  // lda=LD54
    const int F = 54, NL = 27;
    int warp = (blockIdx.x * blockDim.x + threadIdx.x) >> 5;
    int lane = threadIdx.x & 31;
    if (warp >= N) return;
    int v = warp;
    int s = indptr[v], e = indptr[v + 1];
    float2 a0 = {0.f, 0.f}, a1 = {0.f, 0.f}, a2 = {0.f, 0.f}, a3 = {0.f, 0.f};
    bool act = lane < NL;
    size_t off2 = (size_t)lane * 2;
    int i = s;
    for (; i + 3 < e; i += 4) {
        int s0 = csrc[i], s1 = csrc[i + 1], s2 = csrc[i + 2], s3 = csrc[i + 3];
        float d0 = dinv[s0], d1 = dinv[s1], d2 = dinv[s2], d3 = dinv[s3];
        if (act) {
            float2 x0 = *reinterpret_cast<const float2*>(x + (size_t)s0 * F + off2);
            float2 x1 = *reinterpret_cast<const float2*>(x + (size_t)s1 * F + off2);
            float2 x2 = *reinterpret_cast<const float2*>(x + (size_t)s2 * F + off2);
            float2 x3 = *reinterpret_cast<const float2*>(x + (size_t)s3 * F + off2);
            a0.x += d0 * x0.x; a0.y += d0 * x0.y;
            a1.x += d1 * x1.x; a1.y += d1 * x1.y;
            a2.x += d2 * x2.x; a2.y += d2 * x2.y;
            a3.x += d3 * x3.x; a3.y += d3 * x3.y;
        }
    }
    for (; i < e; i++) {
        int s0 = csrc[i];
        float d0 = dinv[s0];
        if (act) {
            float2 x0 = *reinterpret_cast<const float2*>(x + (size_t)s0 * F + off2);
            a0.x += d0 * x0.x; a0.y += d0 * x0.y;
        }
    }
    if (act) {
        float dv = dinv[v];
        float2 xv = *reinterpret_cast<const float2*>(x + (size_t)v * F + off2);
        float2 r;
        r.x = dv * ((a0.x + a1.x) + (a2.x + a3.x) + dv * xv.x);
        r.y = dv * ((a0.y + a1.y) + (a2.y + a3.y) + dv * xv.y);
        *reinterpret_cast<float2*>(out + (size_t)v * LD54 + off2) = r;
    }
}

__global__ void gather54_pre_kernel(const float* __restrict__ hs,  // lda=LD54, pre-scaled
                                    const int* __restrict__ indptr,
                                    const int* __restrict__ csrc,
                                    const float* __restrict__ dinv,
                                    float* __restrict__ out, int N) {  // lda=LD54
    const int NL = 27;
    int warp = (blockIdx.x * blockDim.x + threadIdx.x) >> 5;
    int lane = threadIdx.x & 31;
    if (warp >= N) return;
    int v = warp;
    int s = indptr[v], e = indptr[v + 1];
    float2 a0 = {0.f, 0.f}, a1 = {0.f, 0.f}, a2 = {0.f, 0.f}, a3 = {0.f, 0.f};
    bool act = lane < NL;
    size_t off2 = (size_t)lane * 2;
    int i = s;
    for (; i + 3 < e; i += 4) {
        int s0 = csrc[i], s1 = csrc[i + 1], s2 = csrc[i + 2], s3 = csrc[i + 3];
        if (act) {
            float2 x0 = *reinterpret_cast<const float2*>(hs + (size_t)s0 * LD54 + off2);
            float2 x1 = *reinterpret_cast<const float2*>(hs + (size_t)s1 * LD54 + off2);
            float2 x2 = *reinterpret_cast<const float2*>(hs + (size_t)s2 * LD54 + off2);
            float2 x3 = *reinterpret_cast<const float2*>(hs + (size_t)s3 * LD54 + off2);
            a0.x += x0.x; a0.y += x0.y;
            a1.x += x1.x; a1.y += x1.y;
            a2.x += x2.x; a2.y += x2.y;
            a3.x += x3.x; a3.y += x3.y;
        }
    }
    for (; i < e; i++) {
        int s0 = csrc[i];
        if (act) {
            float2 x0 = *reinterpret_cast<const float2*>(hs + (size_t)s0 * LD54 + off2);
            a0.x += x0.x; a0.y += x0.y;
        }
    }
    if (act) {
        float dv = dinv[v];
        float2 xv = *reinterpret_cast<const float2*>(hs + (size_t)v * LD54 + off2);
        float2 r;
        r.x = dv * ((a0.x + a1.x) + (a2.x + a3.x) + xv.x);
        r.y = dv * ((a0.y + a1.y) + (a2.y + a3.y) + xv.y);
        *reinterpret_cast<float2*>(out + (size_t)v * LD54 + off2) = r;
    }
}

__global__ void gather108_pre_kernel(const float* __restrict__ hs,  // lda=LD108, pre-scaled
                                     const int* __restrict__ indptr,
                                     const int* __restrict__ csrc,
                                     const float* __restrict__ dinv,
                                     float* __restrict__ out, int N) {  // lda=LD108
    const int NL = 27;
    int warp = (blockIdx.x * blockDim.x + threadIdx.x) >> 5;
    int lane = threadIdx.x & 31;
    if (warp >= N) return;
    int v = warp;
    int s = indptr[v], e = indptr[v + 1];
    float4 a0 = {0.f, 0.f, 0.f, 0.f}, a1 = {0.f, 0.f, 0.f, 0.f};
    float4 a2 = {0.f, 0.f, 0.f, 0.f}, a3 = {0.f, 0.f, 0.f, 0.f};
    bool act = lane < NL;
    size_t off4 = (size_t)lane * 4;
    int i = s;
    for (; i + 3 < e; i += 4) {
        int s0 = csrc[i], s1 = csrc[i + 1], s2 = csrc[i + 2], s3 = csrc[i + 3];
        if (act) {
            float4 x0 = *reinterpret_cast<const float4*>(hs + (size_t)s0 * LD108 + off4);
            float4 x1 = *reinterpret_cast<const float4*>(hs + (size_t)s1 * LD108 + off4);
            float4 x2 = *reinterpret_cast<const float4*>(hs + (size_t)s2 * LD108 + off4);
            float4 x3 = *reinterpret_cast<const float4*>(hs + (size_t)s3 * LD108 + off4);
            a0.x += x0.x; a0.y += x0.y; a0.z += x0.z; a0.w += x0.w;
            a1.x += x1.x; a1.y += x1.y; a1.z += x1.z; a1.w += x1.w;
            a2.x += x2.x; a2.y += x2.y; a2.z += x2.z; a2.w += x2.w;
            a3.x += x3.x; a3.y += x3.y; a3.z += x3.z; a3.w += x3.w;
        }
    }
    for (; i < e; i++) {
        int s0 = csrc[i];
        if (act) {
            float4 x0 = *reinterpret_cast<const float4*>(hs + (size_t)s0 * LD108 + off4);
            a0.x += x0.x; a0.y += x0.y; a0.z += x0.z; a0.w += x0.w;
        }
    }
    if (act) {
        float dv = dinv[v];
        float4 xv = *reinterpret_cast<const float4*>(hs + (size_t)v * LD108 + off4);
        float4 r;
        r.x = dv * ((a0.x + a1.x) + (a2.x + a3.x) + xv.x);
        r.y = dv * ((a0.y + a1.y) + (a2.y + a3.y) + xv.y);
        r.z = dv * ((a0.z + a1.z) + (a2.z + a3.z) + xv.z);
        r.w = dv * ((a0.w + a1.w) + (a2.w + a3.w) + xv.w);
        *reinterpret_cast<float4*>(out + (size_t)v * LD108 + off4) = r;
    }
}

// ---------------------------------------------------------------------------
// SGEMM 64x64x16, 4x4 microtile with packed f32x2 FMA (FFMA2), 256 threads.
// C[M,Nc](ldc) = A[M,K](lda) @ B[K,Nc](ldb) (+bias)(relu)(*dinv[row])
// ---------------------------------------------------------------------------
template <bool RELU_OUT, bool BIAS, bool SCALE>
__global__ void gemm_kernel(const float* __restrict__ A, int lda,
                            const float* __restrict__ B, int ldb,
                            const float* __restrict__ bias,
                            const float* __restrict__ dinvv,
                            float* __restrict__ C, int ldc,
                            int M, int K, int Nc) {
    const int BM = 64, BN = 64, BK = 16;
    __shared__ __align__(16) float As[BK][BM + 4];
    __shared__ __align__(16) float Bs[BK][BN];

    int block_row = blockIdx.y * BM;
    int block_col = blockIdx.x * BN;
    int tid = threadIdx.x;
    int tr = tid / 16;
    int tc = tid % 16;

    // Packed accumulators: 4 rows x 2 col-pairs (each pair = 2 fp32)
    unsigned long long accp[4][2] = {};

    for (int k0 = 0; k0 < K; k0 += BK) {
        #pragma unroll
        for (int i = tid; i < BM * BK; i += 256) {
            int r = i / BK, c = i % BK;
            int gr = block_row + r, gk = k0 + c;
            As[c][r] = (gr < M && gk < K) ? A[(size_t)gr * lda + gk] : 0.f;
        }
        #pragma unroll
        for (int i = tid; i < BK * BN; i += 256) {
            int r = i / BN, c = i % BN;
            int gk = k0 + r, gc = block_col + c;
            Bs[r][c] = (gk < K && gc < Nc) ? B[(size_t)gk * ldb + gc] : 0.f;
        }
        __syncthreads();

        #pragma unroll
        for (int k = 0; k < BK; k++) {
            float4 a = *reinterpret_cast<const float4*>(&As[k][tr * 4]);
            ulonglong2 bp = *reinterpret_cast<const ulonglong2*>(&Bs[k][tc * 4]);
            float av[4] = {a.x, a.y, a.z, a.w};
            #pragma unroll
            for (int i = 0; i < 4; i++) {
                unsigned long long ap;
                uint32_t ai = __float_as_uint(av[i]);
                asm("mov.b64 %0, {%1, %1};" : "=l"(ap) : "r"(ai));
                FMA_F32X2(accp[i][0], ap, bp.x, accp[i][0]);
                FMA_F32X2(accp[i][1], ap, bp.y, accp[i][1]);
            }
        }
        __syncthreads();
    }

    #pragma unroll
    for (int i = 0; i < 4; i++) {
        int gr = block_row + tr * 4 + i;
        if (gr >= M) continue;
        float sc = SCALE ? dinvv[gr] : 1.0f;
        float vals[4];
        #pragma unroll
        for (int jp = 0; jp < 2; jp++) {
            uint32_t lo, hi;
            asm("mov.b64 {%0, %1}, %2;" : "=r"(lo), "=r"(hi) : "l"(accp[i][jp]));
            vals[jp * 2]     = __uint_as_float(lo);
            vals[jp * 2 + 1] = __uint_as_float(hi);
        }
        #pragma unroll
        for (int j = 0; j < 4; j++) {
            int gc = block_col + tc * 4 + j;
            if (gc >= Nc) continue;
            float v = vals[j];
            if (BIAS) v += bias[gc];
            if (RELU_OUT) v = fmaxf(v, 0.f);
            if (SCALE) v *= sc;
            C[(size_t)gr * ldc + gc] = v;
        }
    }
}

// ---------------------------------------------------------------------------
// Per-graph mean pool. One block per graph, sorted batch. h stride LD216.
// ---------------------------------------------------------------------------
__global__ void pool_kernel(const float* __restrict__ h, const int* __restrict__ batch,
                            float* __restrict__ pooled, int N, int F) {
    int g = blockIdx.x;
    int lo = 0, hi = N;
    while (lo < hi) { int m = (lo + hi) >> 1; if (batch[m] < g) lo = m + 1; else hi = m; }
    int start = lo;
    lo = start; hi = N;
    while (lo < hi) { int m = (lo + hi) >> 1; if (batch[m] < g + 1) lo = m + 1; else hi = m; }
    int end = lo;

    int f = threadIdx.x;
    if (f >= F) return;
    float acc = 0.f;
    for (int v = start; v < end; v++)
        acc += h[(size_t)v * LD216 + f];
    float cnt = (float)(end - start);
    pooled[g * F + f] = acc / fmaxf(cnt, 1.0f);
}

// ---------------------------------------------------------------------------
// Launch
// ---------------------------------------------------------------------------
static inline dim3 ggrid(int M, int Nc) {
    return dim3((Nc + 63) / 64, (M + 63) / 64);
}

extern "C" void kernel_launch(void* const* d_in, const int* in_sizes, int n_in,
                              void* d_out, int out_size) {
    const float* x    = (const float*)d_in[0];
    const int*   ei   = (const int*)d_in[1];
    const int*   batch= (const int*)d_in[2];
    const float* W1   = (const float*)d_in[3];
    const float* b1   = (const float*)d_in[4];
    const float* W2   = (const float*)d_in[5];
    const float* b2   = (const float*)d_in[6];
    const float* W3   = (const float*)d_in[7];
    const float* b3   = (const float*)d_in[8];
    const float* Wf1  = (const float*)d_in[9];
    const float* bf1  = (const float*)d_in[10];
    const float* Wf2  = (const float*)d_in[11];
    const float* bf2  = (const float*)d_in[12];

    int N = in_sizes[0] / 54;
    int E = in_sizes[1] / 2;
    int G = out_size / 128;
    const int* row = ei;
    const int* col = ei + E;

    float *bufA, *bufB, *dinv, *pooled, *fc1;
    int *counts, *indptr, *cursor, *csrc, *blockSums, *done;
    cudaGetSymbolAddress((void**)&bufA, g_bufA);
    cudaGetSymbolAddress((void**)&bufB, g_bufB);
    cudaGetSymbolAddress((void**)&dinv, g_dinv);
    cudaGetSymbolAddress((void**)&pooled, g_pooled);
    cudaGetSymbolAddress((void**)&fc1, g_fc1);
    cudaGetSymbolAddress((void**)&counts, g_counts);
    cudaGetSymbolAddress((void**)&indptr, g_indptr);
    cudaGetSymbolAddress((void**)&cursor, g_cursor);
    cudaGetSymbolAddress((void**)&csrc, g_csrc);
    cudaGetSymbolAddress((void**)&blockSums, g_blockSums);
    cudaGetSymbolAddress((void**)&done, g_done);

    const int T = 256;
    int nb = (N + SCAN_T - 1) / SCAN_T;
    int gatherGrid = (N + 7) / 8;

    // --- CSR build ---
    zero_counts_kernel<<<(N + T - 1) / T, T>>>(counts, done, N);
    count_kernel<<<(E + T - 1) / T, T>>>(col, counts, E);
    bsum_scan_kernel<<<nb, SCAN_T>>>(counts, blockSums, done, N, nb);
    scan_write_dinv_kernel<<<nb, SCAN_T>>>(counts, blockSums, indptr, cursor, dinv, N);
    fill_kernel<<<(E + T - 1) / T, T>>>(row, col, cursor, csrc, E);

    // --- Layer 1 ---
    gather54_l1_kernel<<<gatherGrid, T>>>(x, indptr, csrc, dinv, bufA, N);
    gemm_kernel<true, true, true><<<ggrid(N, 54), 256>>>(bufA, LD54, W1, 54, b1, dinv, bufB, LD54, N, 54, 54);

    // --- Layer 2 ---
    gather54_pre_kernel<<<gatherGrid, T>>>(bufB, indptr, csrc, dinv, bufA, N);
    gemm_kernel<true, true, true><<<ggrid(N, 108), 256>>>(bufA, LD54, W2, 108, b2, dinv, bufB, LD108, N, 54, 108);

    // --- Layer 3 (no output scale; feeds pooling) ---
    gather108_pre_kernel<<<gatherGrid, T>>>(bufB, indptr, csrc, dinv, bufA, N);
    gemm_kernel<true, true, false><<<ggrid(N, 216), 256>>>(bufA, LD108, W3, 216, b3, nullptr, bufB, LD216, N, 108, 216);

    // --- Global mean pool ---
    pool_kernel<<<G, 256>>>(bufB, batch, pooled, N, 216);

    // --- MLP head ---
    gemm_kernel<true, true, false><<<ggrid(G, 1024), 256>>>(pooled, 216, Wf1, 1024, bf1, nullptr, fc1, 1024, G, 216, 1024);
    gemm_kernel<false, true, false><<<ggrid(G, 128), 256>>>(fc1, 1024, Wf2, 128, bf2, nullptr, (float*)d_out, 128, G, 1024, 128);
}

// round 14
// speedup vs baseline: 1.6178x; 1.5962x over previous
#include <cuda_runtime.h>
#include <cuda_bf16.h>
#include <cstdint>

#define MAX_N 100000
#define MAX_E 1600000
#define MAX_G 256
#define SCAN_T 512

// Padded feature strides (128B-line aligned rows)
#define LD54  64
#define LD108 128
#define LD216 224

// Packed fp32x2 FMA (B300 FFMA2): d = a*b + c elementwise on packed pairs.
#define FMA_F32X2(d, a, b, c) \
    asm("fma.rn.f32x2 %0, %1, %2, %3;" : "=l"(d) : "l"(a), "l"(b), "l"(c))

// ---------------------------------------------------------------------------
// Static scratch (16B aligned for vector access)
// ---------------------------------------------------------------------------
__device__ __align__(16) float g_bufA[MAX_N * LD216];
__device__ __align__(16) float g_bufB[MAX_N * LD216];
__device__ __align__(16) float g_dinv[MAX_N];
__device__ __align__(16) float g_pooled[MAX_G * 216 + 64];
__device__ __align__(16) float g_fc1[MAX_G * 1024 + 64];
__device__ __align__(16) float g_W1p[54 * LD54];   // W1 padded to ldb=64
__device__ int   g_counts[MAX_N];
__device__ int   g_indptr[MAX_N + 1];
__device__ int   g_cursor[MAX_N];
__device__ int   g_blockSums[(MAX_N + SCAN_T - 1) / SCAN_T];
__device__ int   g_done;
__device__ int   g_csrc[MAX_E];

// ---------------------------------------------------------------------------
// W1 padding: W1p[k*64 + n] = W1[k*54 + n]
// ---------------------------------------------------------------------------
__global__ void pad_w1_kernel(const float* __restrict__ W1, float* __restrict__ W1p) {
    int i = blockIdx.x * blockDim.x + threadIdx.x;
    if (i >= 54 * LD54) return;
    int k = i / LD54, n = i % LD54;
    W1p[i] = (n < 54) ? W1[k * 54 + n] : 0.f;
}

// ---------------------------------------------------------------------------
// CSR construction
// ---------------------------------------------------------------------------
__global__ void zero_counts_kernel(int* counts, int* done, int N) {
    int i = blockIdx.x * blockDim.x + threadIdx.x;
    if (i < N) counts[i] = 0;
    if (i == 0) *done = 0;
}

__global__ void count_kernel(const int* __restrict__ col, int* counts, int E) {
    int i = blockIdx.x * blockDim.x + threadIdx.x;
    if (i < E) atomicAdd(&counts[col[i]], 1);
}

__global__ void bsum_scan_kernel(const int* __restrict__ counts, int* blockSums,
                                 int* done, int N, int nb) {
    __shared__ int s[SCAN_T];
    __shared__ bool last;
    int tid = threadIdx.x;
    int i = blockIdx.x * SCAN_T + tid;
    s[tid] = (i < N) ? counts[i] : 0;
    __syncthreads();
    #pragma unroll
    for (int off = SCAN_T / 2; off > 0; off >>= 1) {
        if (tid < off) s[tid] += s[tid + off];
        __syncthreads();
    }
    if (tid == 0) {
        blockSums[blockIdx.x] = s[0];
        __threadfence();
        int p = atomicAdd(done, 1);
        last = (p == nb - 1);
    }
    __syncthreads();
    if (!last) return;
    int v = (tid < nb) ? blockSums[tid] : 0;
    s[tid] = v;
    __syncthreads();
    #pragma unroll
    for (int off = 1; off < SCAN_T; off <<= 1) {
        int u = (tid >= off) ? s[tid - off] : 0;
        __syncthreads();
        s[tid] += u;
        __syncthreads();
    }
    if (tid < nb) blockSums[tid] = s[tid] - v;
}

__global__ void scan_write_dinv_kernel(const int* __restrict__ counts, const int* __restrict__ blockSums,
                                       int* __restrict__ indptr, int* __restrict__ cursor,
                                       float* __restrict__ dinv, int N) {
    __shared__ int s[SCAN_T];
    int tid = threadIdx.x;
    int i = blockIdx.x * SCAN_T + tid;
    int v = (i < N) ? counts[i] : 0;
    s[tid] = v;
    __syncthreads();
    #pragma unroll
    for (int off = 1; off < SCAN_T; off <<= 1) {
        int u = (tid >= off) ? s[tid - off] : 0;
        __syncthreads();
        s[tid] += u;
        __syncthreads();
    }
    int excl = blockSums[blockIdx.x] + s[tid] - v;
    if (i < N) {
        indptr[i] = excl;
        cursor[i] = excl;
        dinv[i] = rsqrtf((float)v + 1.0f);
    }
    if (i == N - 1) indptr[N] = excl + v;
}

__global__ void fill_kernel(const int* __restrict__ row, const int* __restrict__ col,
                            int* cursor, int* __restrict__ csrc, int E) {
    int e = blockIdx.x * blockDim.x + threadIdx.x;
    if (e >= E) return;
    int pos = atomicAdd(&cursor[col[e]], 1);
    csrc[pos] = row[e];
}

// ---------------------------------------------------------------------------
// Gathers (unchanged — control variables).
// ---------------------------------------------------------------------------
__global__ void gather54_l1_kernel(const float* __restrict__ x,
                                   const int* __restrict__ indptr,
                                   const int* __restrict__ csrc,
                                   const float* __restrict__ dinv,
                                   float* __restrict__ out, int N) {
    const int F = 54, NL = 27;
    int warp = (blockIdx.x * blockDim.x + threadIdx.x) >> 5;
    int lane = threadIdx.x & 31;
    if (warp >= N) return;
    int v = warp;
    int s = indptr[v], e = indptr[v + 1];
    float2 a0 = {0.f, 0.f}, a1 = {0.f, 0.f}, a2 = {0.f, 0.f}, a3 = {0.f, 0.f};
    bool act = lane < NL;
    size_t off2 = (size_t)lane * 2;
    int i = s;
    for (; i + 3 < e; i += 4) {
        int s0 = csrc[i], s1 = csrc[i + 1], s2 = csrc[i + 2], s3 = csrc[i + 3];
        float d0 = dinv[s0], d1 = dinv[s1], d2 = dinv[s2], d3 = dinv[s3];
        if (act) {
            float2 x0 = *reinterpret_cast<const float2*>(x + (size_t)s0 * F + off2);
            float2 x1 = *reinterpret_cast<const float2*>(x + (size_t)s1 * F + off2);
            float2 x2 = *reinterpret_cast<const float2*>(x + (size_t)s2 * F + off2);
            float2 x3 = *reinterpret_cast<const float2*>(x + (size_t)s3 * F + off2);
            a0.x += d0 * x0.x; a0.y += d0 * x0.y;
            a1.x += d1 * x1.x; a1.y += d1 * x1.y;
            a2.x += d2 * x2.x; a2.y += d2 * x2.y;
            a3.x += d3 * x3.x; a3.y += d3 * x3.y;
        }
    }
    for (; i < e; i++) {
        int s0 = csrc[i];
        float d0 = dinv[s0];
        if (act) {
            float2 x0 = *reinterpret_cast<const float2*>(x + (size_t)s0 * F + off2);
            a0.x += d0 * x0.x; a0.y += d0 * x0.y;
        }
    }
    if (act) {
        float dv = dinv[v];
        float2 xv = *reinterpret_cast<const float2*>(x + (size_t)v * F + off2);
        float2 r;
        r.x = dv * ((a0.x + a1.x) + (a2.x + a3.x) + dv * xv.x);
        r.y = dv * ((a0.y + a1.y) + (a2.y + a3.y) + dv * xv.y);
        *reinterpret_cast<float2*>(out + (size_t)v * LD54 + off2) = r;
    }
}

__global__ void gather54_pre_kernel(const float* __restrict__ hs,
                                    const int* __restrict__ indptr,
                                    const int* __restrict__ csrc,
                                    const float* __restrict__ dinv,
                                    float* __restrict__ out, int N) {
    const int NL = 27;
    int warp = (blockIdx.x * blockDim.x + threadIdx.x) >> 5;
    int lane = threadIdx.x & 31;
    if (warp >= N) return;
    int v = warp;
    int s = indptr[v], e = indptr[v + 1];
    float2 a0 = {0.f, 0.f}, a1 = {0.f, 0.f}, a2 = {0.f, 0.f}, a3 = {0.f, 0.f};
    bool act = lane < NL;
    size_t off2 = (size_t)lane * 2;
    int i = s;
    for (; i + 3 < e; i += 4) {
        int s0 = csrc[i], s1 = csrc[i + 1], s2 = csrc[i + 2], s3 = csrc[i + 3];
        if (act) {
            float2 x0 = *reinterpret_cast<const float2*>(hs + (size_t)s0 * LD54 + off2);
            float2 x1 = *reinterpret_cast<const float2*>(hs + (size_t)s1 * LD54 + off2);
            float2 x2 = *reinterpret_cast<const float2*>(hs + (size_t)s2 * LD54 + off2);
            float2 x3 = *reinterpret_cast<const float2*>(hs + (size_t)s3 * LD54 + off2);
            a0.x += x0.x; a0.y += x0.y;
            a1.x += x1.x; a1.y += x1.y;
            a2.x += x2.x; a2.y += x2.y;
            a3.x += x3.x; a3.y += x3.y;
        }
    }
    for (; i < e; i++) {
        int s0 = csrc[i];
        if (act) {
            float2 x0 = *reinterpret_cast<const float2*>(hs + (size_t)s0 * LD54 + off2);
            a0.x += x0.x; a0.y += x0.y;
        }
    }
    if (act) {
        float dv = dinv[v];
        float2 xv = *reinterpret_cast<const float2*>(hs + (size_t)v * LD54 + off2);
        float2 r;
        r.x = dv * ((a0.x + a1.x) + (a2.x + a3.x) + xv.x);
        r.y = dv * ((a0.y + a1.y) + (a2.y + a3.y) + xv.y);
        *reinterpret_cast<float2*>(out + (size_t)v * LD54 + off2) = r;
    }
}

__global__ void gather108_pre_kernel(const float* __restrict__ hs,
                                     const int* __restrict__ indptr,
                                     const int* __restrict__ csrc,
                                     const float* __restrict__ dinv,
                                     float* __restrict__ out, int N) {
    const int NL = 27;
    int warp = (blockIdx.x * blockDim.x + threadIdx.x) >> 5;
    int lane = threadIdx.x & 31;
    if (warp >= N) return;
    int v = warp;
    int s = indptr[v], e = indptr[v + 1];
    float4 a0 = {0.f, 0.f, 0.f, 0.f}, a1 = {0.f, 0.f, 0.f, 0.f};
    float4 a2 = {0.f, 0.f, 0.f, 0.f}, a3 = {0.f, 0.f, 0.f, 0.f};
    bool act = lane < NL;
    size_t off4 = (size_t)lane * 4;
    int i = s;
    for (; i + 3 < e; i += 4) {
        int s0 = csrc[i], s1 = csrc[i + 1], s2 = csrc[i + 2], s3 = csrc[i + 3];
        if (act) {
            float4 x0 = *reinterpret_cast<const float4*>(hs + (size_t)s0 * LD108 + off4);
            float4 x1 = *reinterpret_cast<const float4*>(hs + (size_t)s1 * LD108 + off4);
            float4 x2 = *reinterpret_cast<const float4*>(hs + (size_t)s2 * LD108 + off4);
            float4 x3 = *reinterpret_cast<const float4*>(hs + (size_t)s3 * LD108 + off4);
            a0.x += x0.x; a0.y += x0.y; a0.z += x0.z; a0.w += x0.w;
            a1.x += x1.x; a1.y += x1.y; a1.z += x1.z; a1.w += x1.w;
            a2.x += x2.x; a2.y += x2.y; a2.z += x2.z; a2.w += x2.w;
            a3.x += x3.x; a3.y += x3.y; a3.z += x3.z; a3.w += x3.w;
        }
    }
    for (; i < e; i++) {
        int s0 = csrc[i];
        if (act) {
            float4 x0 = *reinterpret_cast<const float4*>(hs + (size_t)s0 * LD108 + off4);
            a0.x += x0.x; a0.y += x0.y; a0.z += x0.z; a0.w += x0.w;
        }
    }
    if (act) {
        float dv = dinv[v];
        float4 xv = *reinterpret_cast<const float4*>(hs + (size_t)v * LD108 + off4);
        float4 r;
        r.x = dv * ((a0.x + a1.x) + (a2.x + a3.x) + xv.x);
        r.y = dv * ((a0.y + a1.y) + (a2.y + a3.y) + xv.y);
        r.z = dv * ((a0.z + a1.z) + (a2.z + a3.z) + xv.z);
        r.w = dv * ((a0.w + a1.w) + (a2.w + a3.w) + xv.w);
        *reinterpret_cast<float4*>(out + (size_t)v * LD108 + off4) = r;
    }
}

// ---------------------------------------------------------------------------
// SGEMM 64x64x16, 4x4 microtile, FFMA2, register-staged software pipeline.
// REQUIRES lda % 4 == 0 and ldb % 4 == 0 (all operands padded accordingly).
// C[M,Nc](ldc) = A[M,K](lda) @ B[K,Nc](ldb) (+bias)(relu)(*dinv[row])
// ---------------------------------------------------------------------------
template <bool RELU_OUT, bool BIAS, bool SCALE>
__global__ __launch_bounds__(256)
void gemm_kernel(const float* __restrict__ A, int lda,
                 const float* __restrict__ B, int ldb,
                 const float* __restrict__ bias,
                 const float* __restrict__ dinvv,
                 float* __restrict__ C, int ldc,
                 int M, int K, int Nc) {
    const int BM = 64, BN = 64, BK = 16;
    __shared__ __align__(16) float As[BK][BM + 4];
    __shared__ __align__(16) float Bs[BK][BN];

    int block_row = blockIdx.y * BM;
    int block_col = blockIdx.x * BN;
    int tid = threadIdx.x;
    int tr = tid / 16;
    int tc = tid % 16;

    int arow = tid >> 2;            // 0..63
    int acg  = (tid & 3) * 4;       // 0,4,8,12 (k offset)
    int brow = tid >> 4;            // 0..15 (k offset)
    int bcol = (tid & 15) * 4;      // 0..60
    int gr_a = block_row + arow;
    int gc_b = block_col + bcol;

    float4 aR, bR;

    auto loadTile = [&](int k0) {
        int gk = k0 + acg;
        if (gr_a < M && gk + 3 < K) {
            aR = *reinterpret_cast<const float4*>(A + (size_t)gr_a * lda + gk);
        } else if (gr_a < M) {
            aR.x = (gk + 0 < K) ? A[(size_t)gr_a * lda + gk + 0] : 0.f;
            aR.y = (gk + 1 < K) ? A[(size_t)gr_a * lda + gk + 1] : 0.f;
            aR.z = (gk + 2 < K) ? A[(size_t)gr_a * lda + gk + 2] : 0.f;
            aR.w = (gk + 3 < K) ? A[(size_t)gr_a * lda + gk + 3] : 0.f;
        } else {
            aR = make_float4(0.f, 0.f, 0.f, 0.f);
        }
        int bk = k0 + brow;
        if (bk < K && gc_b + 3 < Nc) {
            bR = *reinterpret_cast<const float4*>(B + (size_t)bk * ldb + gc_b);
        } else if (bk < K) {
            bR.x = (gc_b + 0 < Nc) ? B[(size_t)bk * ldb + gc_b + 0] : 0.f;
            bR.y = (gc_b + 1 < Nc) ? B[(size_t)bk * ldb + gc_b + 1] : 0.f;
            bR.z = (gc_b + 2 < Nc) ? B[(size_t)bk * ldb + gc_b + 2] : 0.f;
            bR.w = (gc_b + 3 < Nc) ? B[(size_t)bk * ldb + gc_b + 3] : 0.f;
        } else {
            bR = make_float4(0.f, 0.f, 0.f, 0.f);
        }
    };
    auto storeTile = [&]() {
        As[acg + 0][arow] = aR.x;
        As[acg + 1][arow] = aR.y;
        As[acg + 2][arow] = aR.z;
        As[acg + 3][arow] = aR.w;
        *reinterpret_cast<float4*>(&Bs[brow][bcol]) = bR;
    };

    unsigned long long accp[4][2] = {};

    int iters = (K + BK - 1) / BK;
    loadTile(0);
    storeTile();
    __syncthreads();

    for (int t = 0; t < iters; t++) {
        bool more = (t + 1 < iters);
        if (more) loadTile((t + 1) * BK);   // issue next LDGs before compute

        #pragma unroll
        for (int k = 0; k < BK; k++) {
            float4 a = *reinterpret_cast<const float4*>(&As[k][tr * 4]);
            ulonglong2 bp = *reinterpret_cast<const ulonglong2*>(&Bs[k][tc * 4]);
            float av[4] = {a.x, a.y, a.z, a.w};
            #pragma unroll
            for (int i = 0; i < 4; i++) {
                unsigned long long ap;
                uint32_t ai = __float_as_uint(av[i]);
                asm("mov.b64 %0, {%1, %1};" : "=l"(ap) : "r"(ai));
                FMA_F32X2(accp[i][0], ap, bp.x, accp[i][0]);
                FMA_F32X2(accp[i][1], ap, bp.y, accp[i][1]);
            }
        }
        __syncthreads();
        if (more) {
            storeTile();
            __syncthreads();
        }
    }

    #pragma unroll
    for (int i = 0; i < 4; i++) {
        int gr = block_row + tr * 4 + i;
        if (gr >= M) continue;
        float sc = SCALE ? dinvv[gr] : 1.0f;
        float vals[4];
        #pragma unroll
        for (int jp = 0; jp < 2; jp++) {
            uint32_t lo, hi;
            asm("mov.b64 {%0, %1}, %2;" : "=r"(lo), "=r"(hi) : "l"(accp[i][jp]));
            vals[jp * 2]     = __uint_as_float(lo);
            vals[jp * 2 + 1] = __uint_as_float(hi);
        }
        #pragma unroll
        for (int j = 0; j < 4; j++) {
            int gc = block_col + tc * 4 + j;
            if (gc >= Nc) continue;
            float v = vals[j];
            if (BIAS) v += bias[gc];
            if (RELU_OUT) v = fmaxf(v, 0.f);
            if (SCALE) v *= sc;
            C[(size_t)gr * ldc + gc] = v;
        }
    }
}

// ---------------------------------------------------------------------------
// Per-graph mean pool. One block per graph, sorted batch. h stride LD216.
// ---------------------------------------------------------------------------
__global__ void pool_kernel(const float* __restrict__ h, const int* __restrict__ batch,
                            float* __restrict__ pooled, int N, int F) {
    int g = blockIdx.x;
    int lo = 0, hi = N;
    while (lo < hi) { int m = (lo + hi) >> 1; if (batch[m] < g) lo = m + 1; else hi = m; }
    int start = lo;
    lo = start; hi = N;
    while (lo < hi) { int m = (lo + hi) >> 1; if (batch[m] < g + 1) lo = m + 1; else hi = m; }
    int end = lo;

    int f = threadIdx.x;
    if (f >= F) return;
    float acc = 0.f;
    for (int v = start; v < end; v++)
        acc += h[(size_t)v * LD216 + f];
    float cnt = (float)(end - start);
    pooled[g * F + f] = acc / fmaxf(cnt, 1.0f);
}

// ---------------------------------------------------------------------------
// Launch
// ---------------------------------------------------------------------------
static inline dim3 ggrid(int M, int Nc) {
    return dim3((Nc + 63) / 64, (M + 63) / 64);
}

extern "C" void kernel_launch(void* const* d_in, const int* in_sizes, int n_in,
                              void* d_out, int out_size) {
    const float* x    = (const float*)d_in[0];
    const int*   ei   = (const int*)d_in[1];
    const int*   batch= (const int*)d_in[2];
    const float* W1   = (const float*)d_in[3];
    const float* b1   = (const float*)d_in[4];
    const float* W2   = (const float*)d_in[5];
    const float* b2   = (const float*)d_in[6];
    const float* W3   = (const float*)d_in[7];
    const float* b3   = (const float*)d_in[8];
    const float* Wf1  = (const float*)d_in[9];
    const float* bf1  = (const float*)d_in[10];
    const float* Wf2  = (const float*)d_in[11];
    const float* bf2  = (const float*)d_in[12];

    int N = in_sizes[0] / 54;
    int E = in_sizes[1] / 2;
    int G = out_size / 128;
    const int* row = ei;
    const int* col = ei + E;

    float *bufA, *bufB, *dinv, *pooled, *fc1, *W1p;
    int *counts, *indptr, *cursor, *csrc, *blockSums, *done;
    cudaGetSymbolAddress((void**)&bufA, g_bufA);
    cudaGetSymbolAddress((void**)&bufB, g_bufB);
    cudaGetSymbolAddress((void**)&dinv, g_dinv);
    cudaGetSymbolAddress((void**)&pooled, g_pooled);
    cudaGetSymbolAddress((void**)&fc1, g_fc1);
    cudaGetSymbolAddress((void**)&W1p, g_W1p);
    cudaGetSymbolAddress((void**)&counts, g_counts);
    cudaGetSymbolAddress((void**)&indptr, g_indptr);
    cudaGetSymbolAddress((void**)&cursor, g_cursor);
    cudaGetSymbolAddress((void**)&csrc, g_csrc);
    cudaGetSymbolAddress((void**)&blockSums, g_blockSums);
    cudaGetSymbolAddress((void**)&done, g_done);

    const int T = 256;
    int nb = (N + SCAN_T - 1) / SCAN_T;
    int gatherGrid = (N + 7) / 8;

    // --- CSR build + W1 padding ---
    zero_counts_kernel<<<(N + T - 1) / T, T>>>(counts, done, N);
    pad_w1_kernel<<<(54 * LD54 + T - 1) / T, T>>>(W1, W1p);
    count_kernel<<<(E + T - 1) / T, T>>>(col, counts, E);
    bsum_scan_kernel<<<nb, SCAN_T>>>(counts, blockSums, done, N, nb);
    scan_write_dinv_kernel<<<nb, SCAN_T>>>(counts, blockSums, indptr, cursor, dinv, N);
    fill_kernel<<<(E + T - 1) / T, T>>>(row, col, cursor, csrc, E);

    // --- Layer 1 (W1 padded to ldb=64 for aligned float4 loads) ---
    gather54_l1_kernel<<<gatherGrid, T>>>(x, indptr, csrc, dinv, bufA, N);
    gemm_kernel<true, true, true><<<ggrid(N, 54), 256>>>(bufA, LD54, W1p, LD54, b1, dinv, bufB, LD54, N, 54, 54);

    // --- Layer 2 (W2 ldb=108, 432B rows: 16B-aligned) ---
    gather54_pre_kernel<<<gatherGrid, T>>>(bufB, indptr, csrc, dinv, bufA, N);
    gemm_kernel<true, true, true><<<ggrid(N, 108), 256>>>(bufA, LD54, W2, 108, b2, dinv, bufB, LD108, N, 54, 108);

    // --- Layer 3 (W3 ldb=216, 864B rows: aligned) ---
    gather108_pre_kernel<<<gatherGrid, T>>>(bufB, indptr, csrc, dinv, bufA, N);
    gemm_kernel<true, true, false><<<ggrid(N, 216), 256>>>(bufA, LD108, W3, 216, b3, nullptr, bufB, LD216, N, 108, 216);

    // --- Global mean pool ---
    pool_kernel<<<G, 256>>>(bufB, batch, pooled, N, 216);

    // --- MLP head (pooled lda=216 aligned; Wf1 ldb=1024; Wf2 ldb=128) ---
    gemm_kernel<true, true, false><<<ggrid(G, 1024), 256>>>(pooled, 216, Wf1, 1024, bf1, nullptr, fc1, 1024, G, 216, 1024);
    gemm_kernel<false, true, false><<<ggrid(G, 128), 256>>>(fc1, 1024, Wf2, 128, bf2, nullptr, (float*)d_out, 128, G, 1024, 128);
}

// round 16
// speedup vs baseline: 1.6180x; 1.0001x over previous
#include <cuda_runtime.h>
#include <cuda_bf16.h>
#include <cstdint>

#define MAX_N 100000
#define MAX_E 1600000
#define MAX_G 256
#define SCAN_T 512

// Padded feature strides (128B-line aligned rows)
#define LD54  64
#define LD108 128
#define LD216 224

// Packed fp32x2 FMA (B300 FFMA2): d = a*b + c elementwise on packed pairs.
#define FMA_F32X2(d, a, b, c) \
    asm("fma.rn.f32x2 %0, %1, %2, %3;" : "=l"(d) : "l"(a), "l"(b), "l"(c))

// ---------------------------------------------------------------------------
// Static scratch (16B aligned for vector access)
// ---------------------------------------------------------------------------
__device__ __align__(16) float g_bufA[MAX_N * LD216];
__device__ __align__(16) float g_bufB[MAX_N * LD216];
__device__ __align__(16) float g_dinv[MAX_N];
__device__ __align__(16) float g_pooled[MAX_G * 216 + 64];
__device__ __align__(16) float g_fc1[MAX_G * 1024 + 64];
__device__ __align__(16) float g_W1p[54 * LD54];   // W1 padded to ldb=64
__device__ int   g_counts[MAX_N];
__device__ int   g_indptr[MAX_N + 1];
__device__ int   g_cursor[MAX_N];
__device__ int   g_blockSums[(MAX_N + SCAN_T - 1) / SCAN_T];
__device__ int   g_done;
__device__ int   g_csrc[MAX_E];

// ---------------------------------------------------------------------------
// W1 padding: W1p[k*64 + n] = W1[k*54 + n]
// ---------------------------------------------------------------------------
__global__ void pad_w1_kernel(const float* __restrict__ W1, float* __restrict__ W1p) {
    int i = blockIdx.x * blockDim.x + threadIdx.x;
    if (i >= 54 * LD54) return;
    int k = i / LD54, n = i % LD54;
    W1p[i] = (n < 54) ? W1[k * 54 + n] : 0.f;
}

// ---------------------------------------------------------------------------
// CSR construction
// ---------------------------------------------------------------------------
__global__ void zero_counts_kernel(int* counts, int* done, int N) {
    int i = blockIdx.x * blockDim.x + threadIdx.x;
    if (i < N) counts[i] = 0;
    if (i == 0) *done = 0;
}

__global__ void count_kernel(const int* __restrict__ col, int* counts, int E) {
    int i = blockIdx.x * blockDim.x + threadIdx.x;
    if (i < E) atomicAdd(&counts[col[i]], 1);
}

__global__ void bsum_scan_kernel(const int* __restrict__ counts, int* blockSums,
                                 int* done, int N, int nb) {
    __shared__ int s[SCAN_T];
    __shared__ bool last;
    int tid = threadIdx.x;
    int i = blockIdx.x * SCAN_T + tid;
    s[tid] = (i < N) ? counts[i] : 0;
    __syncthreads();
    #pragma unroll
    for (int off = SCAN_T / 2; off > 0; off >>= 1) {
        if (tid < off) s[tid] += s[tid + off];
        __syncthreads();
    }
    if (tid == 0) {
        blockSums[blockIdx.x] = s[0];
        __threadfence();
        int p = atomicAdd(done, 1);
        last = (p == nb - 1);
    }
    __syncthreads();
    if (!last) return;
    int v = (tid < nb) ? blockSums[tid] : 0;
    s[tid] = v;
    __syncthreads();
    #pragma unroll
    for (int off = 1; off < SCAN_T; off <<= 1) {
        int u = (tid >= off) ? s[tid - off] : 0;
        __syncthreads();
        s[tid] += u;
        __syncthreads();
    }
    if (tid < nb) blockSums[tid] = s[tid] - v;
}

__global__ void scan_write_dinv_kernel(const int* __restrict__ counts, const int* __restrict__ blockSums,
                                       int* __restrict__ indptr, int* __restrict__ cursor,
                                       float* __restrict__ dinv, int N) {
    __shared__ int s[SCAN_T];
    int tid = threadIdx.x;
    int i = blockIdx.x * SCAN_T + tid;
    int v = (i < N) ? counts[i] : 0;
    s[tid] = v;
    __syncthreads();
    #pragma unroll
    for (int off = 1; off < SCAN_T; off <<= 1) {
        int u = (tid >= off) ? s[tid - off] : 0;
        __syncthreads();
        s[tid] += u;
        __syncthreads();
    }
    int excl = blockSums[blockIdx.x] + s[tid] - v;
    if (i < N) {
        indptr[i] = excl;
        cursor[i] = excl;
        dinv[i] = rsqrtf((float)v + 1.0f);
    }
    if (i == N - 1) indptr[N] = excl + v;
}

__global__ void fill_kernel(const int* __restrict__ row, const int* __restrict__ col,
                            int* cursor, int* __restrict__ csrc, int E) {
    int e = blockIdx.x * blockDim.x + threadIdx.x;
    if (e >= E) return;
    int pos = atomicAdd(&cursor[col[e]], 1);
    csrc[pos] = row[e];
}

// ---------------------------------------------------------------------------
// Gathers. Streaming (__stcs) output stores keep the random-read source
// resident in L2.
// ---------------------------------------------------------------------------
__global__ void gather54_l1_kernel(const float* __restrict__ x,
                                   const int* __restrict__ indptr,
                                   const int* __restrict__ csrc,
                                   const float* __restrict__ dinv,
                                   float* __restrict__ out, int N) {
    const int F = 54, NL = 27;
    int warp = (blockIdx.x * blockDim.x + threadIdx.x) >> 5;
    int lane = threadIdx.x & 31;
    if (warp >= N) return;
    int v = warp;
    int s = indptr[v], e = indptr[v + 1];
    float2 a0 = {0.f, 0.f}, a1 = {0.f, 0.f}, a2 = {0.f, 0.f}, a3 = {0.f, 0.f};
    bool act = lane < NL;
    size_t off2 = (size_t)lane * 2;
    int i = s;
    for (; i + 3 < e; i += 4) {
        int s0 = csrc[i], s1 = csrc[i + 1], s2 = csrc[i + 2], s3 = csrc[i + 3];
        float d0 = dinv[s0], d1 = dinv[s1], d2 = dinv[s2], d3 = dinv[s3];
        if (act) {
            float2 x0 = *reinterpret_cast<const float2*>(x + (size_t)s0 * F + off2);
            float2 x1 = *reinterpret_cast<const float2*>(x + (size_t)s1 * F + off2);
            float2 x2 = *reinterpret_cast<const float2*>(x + (size_t)s2 * F + off2);
            float2 x3 = *reinterpret_cast<const float2*>(x + (size_t)s3 * F + off2);
            a0.x += d0 * x0.x; a0.y += d0 * x0.y;
            a1.x += d1 * x1.x; a1.y += d1 * x1.y;
            a2.x += d2 * x2.x; a2.y += d2 * x2.y;
            a3.x += d3 * x3.x; a3.y += d3 * x3.y;
        }
    }
    for (; i < e; i++) {
        int s0 = csrc[i];
        float d0 = dinv[s0];
        if (act) {
            float2 x0 = *reinterpret_cast<const float2*>(x + (size_t)s0 * F + off2);
            a0.x += d0 * x0.x; a0.y += d0 * x0.y;
        }
    }
    if (act) {
        float dv = dinv[v];
        float2 xv = *reinterpret_cast<const float2*>(x + (size_t)v * F + off2);
        float2 r;
        r.x = dv * ((a0.x + a1.x) + (a2.x + a3.x) + dv * xv.x);
        r.y = dv * ((a0.y + a1.y) + (a2.y + a3.y) + dv * xv.y);
        __stcs(reinterpret_cast<float2*>(out + (size_t)v * LD54 + off2), r);
    }
}

__global__ void gather54_pre_kernel(const float* __restrict__ hs,
                                    const int* __restrict__ indptr,
                                    const int* __restrict__ csrc,
                                    const float* __restrict__ dinv,
                                    float* __restrict__ out, int N) {
    const int NL = 27;
    int warp = (blockIdx.x * blockDim.x + threadIdx.x) >> 5;
    int lane = threadIdx.x & 31;
    if (warp >= N) return;
    int v = warp;
    int s = indptr[v], e = indptr[v + 1];
    float2 a0 = {0.f, 0.f}, a1 = {0.f, 0.f}, a2 = {0.f, 0.f}, a3 = {0.f, 0.f};
    bool act = lane < NL;
    size_t off2 = (size_t)lane * 2;
    int i = s;
    for (; i + 3 < e; i += 4) {
        int s0 = csrc[i], s1 = csrc[i + 1], s2 = csrc[i + 2], s3 = csrc[i + 3];
        if (act) {
            float2 x0 = *reinterpret_cast<const float2*>(hs + (size_t)s0 * LD54 + off2);
            float2 x1 = *reinterpret_cast<const float2*>(hs + (size_t)s1 * LD54 + off2);
            float2 x2 = *reinterpret_cast<const float2*>(hs + (size_t)s2 * LD54 + off2);
            float2 x3 = *reinterpret_cast<const float2*>(hs + (size_t)s3 * LD54 + off2);
            a0.x += x0.x; a0.y += x0.y;
            a1.x += x1.x; a1.y += x1.y;
            a2.x += x2.x; a2.y += x2.y;
            a3.x += x3.x; a3.y += x3.y;
        }
    }
    for (; i < e; i++) {
        int s0 = csrc[i];
        if (act) {
            float2 x0 = *reinterpret_cast<const float2*>(hs + (size_t)s0 * LD54 + off2);
            a0.x += x0.x; a0.y += x0.y;
        }
    }
    if (act) {
        float dv = dinv[v];
        float2 xv = *reinterpret_cast<const float2*>(hs + (size_t)v * LD54 + off2);
        float2 r;
        r.x = dv * ((a0.x + a1.x) + (a2.x + a3.x) + xv.x);
        r.y = dv * ((a0.y + a1.y) + (a2.y + a3.y) + xv.y);
        __stcs(reinterpret_cast<float2*>(out + (size_t)v * LD54 + off2), r);
    }
}

__global__ void gather108_pre_kernel(const float* __restrict__ hs,
                                     const int* __restrict__ indptr,
                                     const int* __restrict__ csrc,
                                     const float* __restrict__ dinv,
                                     float* __restrict__ out, int N) {
    const int NL = 27;
    int warp = (blockIdx.x * blockDim.x + threadIdx.x) >> 5;
    int lane = threadIdx.x & 31;
    if (warp >= N) return;
    int v = warp;
    int s = indptr[v], e = indptr[v + 1];
    float4 a0 = {0.f, 0.f, 0.f, 0.f}, a1 = {0.f, 0.f, 0.f, 0.f};
    float4 a2 = {0.f, 0.f, 0.f, 0.f}, a3 = {0.f, 0.f, 0.f, 0.f};
    bool act = lane < NL;
    size_t off4 = (size_t)lane * 4;
    int i = s;
    for (; i + 3 < e; i += 4) {
        int s0 = csrc[i], s1 = csrc[i + 1], s2 = csrc[i + 2], s3 = csrc[i + 3];
        if (act) {
            float4 x0 = *reinterpret_cast<const float4*>(hs + (size_t)s0 * LD108 + off4);
            float4 x1 = *reinterpret_cast<const float4*>(hs + (size_t)s1 * LD108 + off4);
            float4 x2 = *reinterpret_cast<const float4*>(hs + (size_t)s2 * LD108 + off4);
            float4 x3 = *reinterpret_cast<const float4*>(hs + (size_t)s3 * LD108 + off4);
            a0.x += x0.x; a0.y += x0.y; a0.z += x0.z; a0.w += x0.w;
            a1.x += x1.x; a1.y += x1.y; a1.z += x1.z; a1.w += x1.w;
            a2.x += x2.x; a2.y += x2.y; a2.z += x2.z; a2.w += x2.w;
            a3.x += x3.x; a3.y += x3.y; a3.z += x3.z; a3.w += x3.w;
        }
    }
    for (; i < e; i++) {
        int s0 = csrc[i];
        if (act) {
            float4 x0 = *reinterpret_cast<const float4*>(hs + (size_t)s0 * LD108 + off4);
            a0.x += x0.x; a0.y += x0.y; a0.z += x0.z; a0.w += x0.w;
        }
    }
    if (act) {
        float dv = dinv[v];
        float4 xv = *reinterpret_cast<const float4*>(hs + (size_t)v * LD108 + off4);
        float4 r;
        r.x = dv * ((a0.x + a1.x) + (a2.x + a3.x) + xv.x);
        r.y = dv * ((a0.y + a1.y) + (a2.y + a3.y) + xv.y);
        r.z = dv * ((a0.z + a1.z) + (a2.z + a3.z) + xv.z);
        r.w = dv * ((a0.w + a1.w) + (a2.w + a3.w) + xv.w);
        __stcs(reinterpret_cast<float4*>(out + (size_t)v * LD108 + off4), r);
    }
}

// ---------------------------------------------------------------------------
// SGEMM 64x64x16, 4x4 microtile, FFMA2, register-staged prefetch +
// double-buffered shared memory (ONE __syncthreads per K-tile).
// REQUIRES lda % 4 == 0 and ldb % 4 == 0.
// C[M,Nc](ldc) = A[M,K](lda) @ B[K,Nc](ldb) (+bias)(relu)(*dinv[row])
// ---------------------------------------------------------------------------
template <bool RELU_OUT, bool BIAS, bool SCALE>
__global__ __launch_bounds__(256)
void gemm_kernel(const float* __restrict__ A, int lda,
                 const float* __restrict__ B, int ldb,
                 const float* __restrict__ bias,
                 const float* __restrict__ dinvv,
                 float* __restrict__ C, int ldc,
                 int M, int K, int Nc) {
    const int BM = 64, BN = 64, BK = 16;
    __shared__ __align__(16) float As[2][BK][BM + 4];
    __shared__ __align__(16) float Bs[2][BK][BN];

    int block_row = blockIdx.y * BM;
    int block_col = blockIdx.x * BN;
    int tid = threadIdx.x;
    int tr = tid / 16;
    int tc = tid % 16;

    int arow = tid >> 2;            // 0..63
    int acg  = (tid & 3) * 4;       // 0,4,8,12 (k offset)
    int brow = tid >> 4;            // 0..15 (k offset)
    int bcol = (tid & 15) * 4;      // 0..60
    int gr_a = block_row + arow;
    int gc_b = block_col + bcol;

    float4 aR, bR;

    auto loadTile = [&](int k0) {
        int gk = k0 + acg;
        if (gr_a < M && gk + 3 < K) {
            aR = *reinterpret_cast<const float4*>(A + (size_t)gr_a * lda + gk);
        } else if (gr_a < M) {
            aR.x = (gk + 0 < K) ? A[(size_t)gr_a * lda + gk + 0] : 0.f;
            aR.y = (gk + 1 < K) ? A[(size_t)gr_a * lda + gk + 1] : 0.f;
            aR.z = (gk + 2 < K) ? A[(size_t)gr_a * lda + gk + 2] : 0.f;
            aR.w = (gk + 3 < K) ? A[(size_t)gr_a * lda + gk + 3] : 0.f;
        } else {
            aR = make_float4(0.f, 0.f, 0.f, 0.f);
        }
        int bk = k0 + brow;
        if (bk < K && gc_b + 3 < Nc) {
            bR = *reinterpret_cast<const float4*>(B + (size_t)bk * ldb + gc_b);
        } else if (bk < K) {
            bR.x = (gc_b + 0 < Nc) ? B[(size_t)bk * ldb + gc_b + 0] : 0.f;
            bR.y = (gc_b + 1 < Nc) ? B[(size_t)bk * ldb + gc_b + 1] : 0.f;
            bR.z = (gc_b + 2 < Nc) ? B[(size_t)bk * ldb + gc_b + 2] : 0.f;
            bR.w = (gc_b + 3 < Nc) ? B[(size_t)bk * ldb + gc_b + 3] : 0.f;
        } else {
            bR = make_float4(0.f, 0.f, 0.f, 0.f);
        }
    };
    auto storeTile = [&](int buf) {
        As[buf][acg + 0][arow] = aR.x;
        As[buf][acg + 1][arow] = aR.y;
        As[buf][acg + 2][arow] = aR.z;
        As[buf][acg + 3][arow] = aR.w;
        *reinterpret_cast<float4*>(&Bs[buf][brow][bcol]) = bR;
    };

    unsigned long long accp[4][2] = {};

    int iters = (K + BK - 1) / BK;
    loadTile(0);
    storeTile(0);
    __syncthreads();

    for (int t = 0; t < iters; t++) {
        int cur = t & 1;
        bool more = (t + 1 < iters);
        if (more) loadTile((t + 1) * BK);   // LDGs in flight across compute

        #pragma unroll
        for (int k = 0; k < BK; k++) {
            float4 a = *reinterpret_cast<const float4*>(&As[cur][k][tr * 4]);
            ulonglong2 bp = *reinterpret_cast<const ulonglong2*>(&Bs[cur][k][tc * 4]);
            float av[4] = {a.x, a.y, a.z, a.w};
            #pragma unroll
            for (int i = 0; i < 4; i++) {
                unsigned long long ap;
                uint32_t ai = __float_as_uint(av[i]);
                asm("mov.b64 %0, {%1, %1};" : "=l"(ap) : "r"(ai));
                FMA_F32X2(accp[i][0], ap, bp.x, accp[i][0]);
                FMA_F32X2(accp[i][1], ap, bp.y, accp[i][1]);
            }
        }
        if (more) {
            storeTile(cur ^ 1);   // other buffer: safe, consumed two iters ago
            __syncthreads();      // single barrier per iteration
        }
    }

    #pragma unroll
    for (int i = 0; i < 4; i++) {
        int gr = block_row + tr * 4 + i;
        if (gr >= M) continue;
        float sc = SCALE ? dinvv[gr] : 1.0f;
        float vals[4];
        #pragma unroll
        for (int jp = 0; jp < 2; jp++) {
            uint32_t lo, hi;
            asm("mov.b64 {%0, %1}, %2;" : "=r"(lo), "=r"(hi) : "l"(accp[i][jp]));
            vals[jp * 2]     = __uint_as_float(lo);
            vals[jp * 2 + 1] = __uint_as_float(hi);
        }
        #pragma unroll
        for (int j = 0; j < 4; j++) {
            int gc = block_col + tc * 4 + j;
            if (gc >= Nc) continue;
            float v = vals[j];
            if (BIAS) v += bias[gc];
            if (RELU_OUT) v = fmaxf(v, 0.f);
            if (SCALE) v *= sc;
            C[(size_t)gr * ldc + gc] = v;
        }
    }
}

// ---------------------------------------------------------------------------
// Per-graph mean pool. One block per graph, sorted batch. h stride LD216.
// ---------------------------------------------------------------------------
__global__ void pool_kernel(const float* __restrict__ h, const int* __restrict__ batch,
                            float* __restrict__ pooled, int N, int F) {
    int g = blockIdx.x;
    int lo = 0, hi = N;
    while (lo < hi) { int m = (lo + hi) >> 1; if (batch[m] < g) lo = m + 1; else hi = m; }
    int start = lo;
    lo = start; hi = N;
    while (lo < hi) { int m = (lo + hi) >> 1; if (batch[m] < g + 1) lo = m + 1; else hi = m; }
    int end = lo;

    int f = threadIdx.x;
    if (f >= F) return;
    float acc = 0.f;
    for (int v = start; v < end; v++)
        acc += h[(size_t)v * LD216 + f];
    float cnt = (float)(end - start);
    pooled[g * F + f] = acc / fmaxf(cnt, 1.0f);
}

// ---------------------------------------------------------------------------
// Launch
// ---------------------------------------------------------------------------
static inline dim3 ggrid(int M, int Nc) {
    return dim3((Nc + 63) / 64, (M + 63) / 64);
}

extern "C" void kernel_launch(void* const* d_in, const int* in_sizes, int n_in,
                              void* d_out, int out_size) {
    const float* x    = (const float*)d_in[0];
    const int*   ei   = (const int*)d_in[1];
    const int*   batch= (const int*)d_in[2];
    const float* W1   = (const float*)d_in[3];
    const float* b1   = (const float*)d_in[4];
    const float* W2   = (const float*)d_in[5];
    const float* b2   = (const float*)d_in[6];
    const float* W3   = (const float*)d_in[7];
    const float* b3   = (const float*)d_in[8];
    const float* Wf1  = (const float*)d_in[9];
    const float* bf1  = (const float*)d_in[10];
    const float* Wf2  = (const float*)d_in[11];
    const float* bf2  = (const float*)d_in[12];

    int N = in_sizes[0] / 54;
    int E = in_sizes[1] / 2;
    int G = out_size / 128;
    const int* row = ei;
    const int* col = ei + E;

    float *bufA, *bufB, *dinv, *pooled, *fc1, *W1p;
    int *counts, *indptr, *cursor, *csrc, *blockSums, *done;
    cudaGetSymbolAddress((void**)&bufA, g_bufA);
    cudaGetSymbolAddress((void**)&bufB, g_bufB);
    cudaGetSymbolAddress((void**)&dinv, g_dinv);
    cudaGetSymbolAddress((void**)&pooled, g_pooled);
    cudaGetSymbolAddress((void**)&fc1, g_fc1);
    cudaGetSymbolAddress((void**)&W1p, g_W1p);
    cudaGetSymbolAddress((void**)&counts, g_counts);
    cudaGetSymbolAddress((void**)&indptr, g_indptr);
    cudaGetSymbolAddress((void**)&cursor, g_cursor);
    cudaGetSymbolAddress((void**)&csrc, g_csrc);
    cudaGetSymbolAddress((void**)&blockSums, g_blockSums);
    cudaGetSymbolAddress((void**)&done, g_done);

    const int T = 256;
    int nb = (N + SCAN_T - 1) / SCAN_T;
    int gatherGrid = (N + 7) / 8;

    // --- CSR build + W1 padding ---
    zero_counts_kernel<<<(N + T - 1) / T, T>>>(counts, done, N);
    pad_w1_kernel<<<(54 * LD54 + T - 1) / T, T>>>(W1, W1p);
    count_kernel<<<(E + T - 1) / T, T>>>(col, counts, E);
    bsum_scan_kernel<<<nb, SCAN_T>>>(counts, blockSums, done, N, nb);
    scan_write_dinv_kernel<<<nb, SCAN_T>>>(counts, blockSums, indptr, cursor, dinv, N);
    fill_kernel<<<(E + T - 1) / T, T>>>(row, col, cursor, csrc, E);

    // --- Layer 1 ---
    gather54_l1_kernel<<<gatherGrid, T>>>(x, indptr, csrc, dinv, bufA, N);
    gemm_kernel<true, true, true><<<ggrid(N, 54), 256>>>(bufA, LD54, W1p, LD54, b1, dinv, bufB, LD54, N, 54, 54);

    // --- Layer 2 ---
    gather54_pre_kernel<<<gatherGrid, T>>>(bufB, indptr, csrc, dinv, bufA, N);
    gemm_kernel<true, true, true><<<ggrid(N, 108), 256>>>(bufA, LD54, W2, 108, b2, dinv, bufB, LD108, N, 54, 108);

    // --- Layer 3 ---
    gather108_pre_kernel<<<gatherGrid, T>>>(bufB, indptr, csrc, dinv, bufA, N);
    gemm_kernel<true, true, false><<<ggrid(N, 216), 256>>>(bufA, LD108, W3, 216, b3, nullptr, bufB, LD216, N, 108, 216);

    // --- Global mean pool ---
    pool_kernel<<<G, 256>>>(bufB, batch, pooled, N, 216);

    // --- MLP head ---
    gemm_kernel<true, true, false><<<ggrid(G, 1024), 256>>>(pooled, 216, Wf1, 1024, bf1, nullptr, fc1, 1024, G, 216, 1024);
    gemm_kernel<false, true, false><<<ggrid(G, 128), 256>>>(fc1, 1024, Wf2, 128, bf2, nullptr, (float*)d_out, 128, G, 1024, 128);
}